// round 12
// baseline (speedup 1.0000x reference)
#include <cuda_runtime.h>
#include <cuda_bf16.h>
#include <cstdint>
#include <cstddef>

// ---------------- problem constants ----------------
static constexpr int Bb  = 4;
static constexpr int L   = 2048;
static constexpr int DM  = 1024;          // d_model
static constexpr int DI  = 2048;          // d_inner
static constexpr int DS  = 16;            // d_state
static constexpr int DTR = 64;            // dt_rank
static constexpr int ROWS = Bb * L;       // 8192
static constexpr int DBC = DTR + 2 * DS;  // 96

// ---------------- scratch (device globals, no allocations) ----------------
__device__ float g_mod[Bb * 3 * DM];                    // scale|shift|gate
__device__ __nv_bfloat16 g_hh[(size_t)ROWS * DM];       // LN-modulated input (bf16)
__device__ float g_xz[(size_t)ROWS * 2 * DI];           // x@W_in  (xm | z)
__device__ float g_xc[(size_t)ROWS * DI];               // conv+silu
__device__ float g_dbc[(size_t)ROWS * DBC];             // dt | B | C
__device__ float g_delta[(size_t)ROWS * DI];            // softplus(dt@W_dt+b)
__device__ __nv_bfloat16 g_ymulh[(size_t)ROWS * DI];    // (scan+u*D)*silu(z) (bf16)
__device__ __nv_bfloat16 g_WinTh[(size_t)(2 * DI) * DM];// W_in^T  bf16 [4096][1024]
__device__ float g_WdtT[(size_t)DI * DTR];              // W_dt^T  fp32 [2048][64]
__device__ __nv_bfloat16 g_WoutTh[(size_t)DM * DI];     // W_out^T bf16 [1024][2048]

// ---------------- helpers ----------------
__device__ __forceinline__ uint32_t smem_u32(const void* p) {
    uint32_t a;
    asm("{ .reg .u64 t; cvta.to.shared.u64 t, %1; cvt.u32.u64 %0, t; }" : "=r"(a) : "l"(p));
    return a;
}
__device__ __forceinline__ void cp_async16(uint32_t dst, const void* src) {
    asm volatile("cp.async.cg.shared.global [%0], [%1], 16;"
                 :: "r"(dst), "l"(__cvta_generic_to_global(src)));
}
#define CP_COMMIT() asm volatile("cp.async.commit_group;" ::: "memory")
#define CP_WAIT1()  asm volatile("cp.async.wait_group 1;" ::: "memory")

__device__ __forceinline__ void mma_tf32(float* c, const uint32_t* a, const uint32_t* b) {
    asm volatile(
        "mma.sync.aligned.m16n8k8.row.col.f32.tf32.tf32.f32 "
        "{%0,%1,%2,%3}, {%4,%5,%6,%7}, {%8,%9}, {%0,%1,%2,%3};"
        : "+f"(c[0]), "+f"(c[1]), "+f"(c[2]), "+f"(c[3])
        : "r"(a[0]), "r"(a[1]), "r"(a[2]), "r"(a[3]), "r"(b[0]), "r"(b[1]));
}
__device__ __forceinline__ void mma_bf16(float* c, const uint32_t* a, const uint32_t* b) {
    asm volatile(
        "mma.sync.aligned.m16n8k16.row.col.f32.bf16.bf16.f32 "
        "{%0,%1,%2,%3}, {%4,%5,%6,%7}, {%8,%9}, {%0,%1,%2,%3};"
        : "+f"(c[0]), "+f"(c[1]), "+f"(c[2]), "+f"(c[3])
        : "r"(a[0]), "r"(a[1]), "r"(a[2]), "r"(a[3]), "r"(b[0]), "r"(b[1]));
}
__device__ __forceinline__ void ldsm_x4(uint32_t* r, uint32_t addr) {
    asm volatile("ldmatrix.sync.aligned.m8n8.x4.shared.b16 {%0,%1,%2,%3}, [%4];"
                 : "=r"(r[0]), "=r"(r[1]), "=r"(r[2]), "=r"(r[3]) : "r"(addr));
}

// ---------------- small kernels ----------------
// fused silu(c) + ada projection: mod = b_ada + silu(c) @ W_ada
__global__ void k_ada(const float* __restrict__ c, const float* __restrict__ W,
                      const float* __restrict__ bias) {
    __shared__ float sc[DM];
    int j = blockIdx.x * blockDim.x + threadIdx.x;   // 0..3071
    int b = blockIdx.y;
    for (int k = threadIdx.x; k < DM; k += blockDim.x) {
        float v = c[b * DM + k];
        sc[k] = v / (1.f + __expf(-v));
    }
    __syncthreads();
    float a[8];
    #pragma unroll
    for (int i = 0; i < 8; i++) a[i] = 0.f;
    for (int k = 0; k < DM; k += 8) {
        #pragma unroll
        for (int i = 0; i < 8; i++)
            a[i] += sc[k + i] * W[(size_t)(k + i) * (3 * DM) + j];
    }
    float s = 0.f;
    #pragma unroll
    for (int i = 0; i < 8; i++) s += a[i];
    g_mod[b * 3 * DM + j] = bias[j] + s;
}

// LayerNorm + (1+scale)*xn + shift -> g_hh (bf16)
__global__ void k_ln(const float* __restrict__ x) {
    int row = blockIdx.x;
    int b = row >> 11;
    const float4* xr = (const float4*)(x + (size_t)row * DM);
    float4 v = xr[threadIdx.x];
    float s = v.x + v.y + v.z + v.w;
    float q = v.x * v.x + v.y * v.y + v.z * v.z + v.w * v.w;
    #pragma unroll
    for (int o = 16; o; o >>= 1) {
        s += __shfl_xor_sync(0xffffffffu, s, o);
        q += __shfl_xor_sync(0xffffffffu, q, o);
    }
    __shared__ float ss[8], sq[8];
    int w = threadIdx.x >> 5;
    if ((threadIdx.x & 31) == 0) { ss[w] = s; sq[w] = q; }
    __syncthreads();
    s = 0.f; q = 0.f;
    #pragma unroll
    for (int i = 0; i < 8; i++) { s += ss[i]; q += sq[i]; }
    float mean = s * (1.f / DM);
    float var  = q * (1.f / DM) - mean * mean;
    float rstd = rsqrtf(var + 1e-6f);
    int col = threadIdx.x * 4;
    float4 sc4 = *(const float4*)(g_mod + b * 3 * DM + col);
    float4 sh4 = *(const float4*)(g_mod + b * 3 * DM + DM + col);
    float o0 = (v.x - mean) * rstd * (1.f + sc4.x) + sh4.x;
    float o1 = (v.y - mean) * rstd * (1.f + sc4.y) + sh4.y;
    float o2 = (v.z - mean) * rstd * (1.f + sc4.z) + sh4.z;
    float o3 = (v.w - mean) * rstd * (1.f + sc4.w) + sh4.w;
    __nv_bfloat162 h0 = __floats2bfloat162_rn(o0, o1);
    __nv_bfloat162 h1 = __floats2bfloat162_rn(o2, o3);
    uint2 u;
    u.x = *(uint32_t*)&h0;
    u.y = *(uint32_t*)&h1;
    *(uint2*)(g_hh + (size_t)row * DM + col) = u;
}

__global__ void k_conv(const float* __restrict__ cw, const float* __restrict__ cb) {
    int i = blockIdx.x * blockDim.x + threadIdx.x;
    if (i >= ROWS * DI) return;
    int d = i & (DI - 1);
    int row = i >> 11;
    int l = row & (L - 1);
    float4 w = *(const float4*)(cw + 4 * d);
    size_t base = (size_t)row * (2 * DI) + d;
    float acc = cb[d] + g_xz[base] * w.w;
    if (l >= 1) acc += g_xz[base - 1 * (2 * DI)] * w.z;
    if (l >= 2) acc += g_xz[base - 2 * (2 * DI)] * w.y;
    if (l >= 3) acc += g_xz[base - 3 * (2 * DI)] * w.x;
    float sil = acc / (1.f + __expf(-acc));
    g_xc[(size_t)row * DI + d] = sil;
}

// 32x32 tiled transpose: fp32 out
__global__ void k_tr(const float* __restrict__ S, float* __restrict__ D, int R, int C) {
    __shared__ float t[32][33];
    int c0 = blockIdx.x * 32, r0 = blockIdx.y * 32;
    #pragma unroll
    for (int j = 0; j < 4; j++)
        t[threadIdx.y + 8 * j][threadIdx.x] =
            S[(size_t)(r0 + threadIdx.y + 8 * j) * C + c0 + threadIdx.x];
    __syncthreads();
    #pragma unroll
    for (int j = 0; j < 4; j++)
        D[(size_t)(c0 + threadIdx.y + 8 * j) * R + r0 + threadIdx.x] =
            t[threadIdx.x][threadIdx.y + 8 * j];
}

// 32x32 tiled transpose: bf16 out
__global__ void k_tr_bf(const float* __restrict__ S, __nv_bfloat16* __restrict__ D, int R, int C) {
    __shared__ float t[32][33];
    int c0 = blockIdx.x * 32, r0 = blockIdx.y * 32;
    #pragma unroll
    for (int j = 0; j < 4; j++)
        t[threadIdx.y + 8 * j][threadIdx.x] =
            S[(size_t)(r0 + threadIdx.y + 8 * j) * C + c0 + threadIdx.x];
    __syncthreads();
    #pragma unroll
    for (int j = 0; j < 4; j++)
        D[(size_t)(c0 + threadIdx.y + 8 * j) * R + r0 + threadIdx.x] =
            __float2bfloat16_rn(t[threadIdx.x][threadIdx.y + 8 * j]);
}

// selective scan: 4 threads per (b,d) channel, 4 states each. bf16 output.
__global__ void k_scan4(const float* __restrict__ Alog, const float* __restrict__ Dskip) {
    int t = blockIdx.x * blockDim.x + threadIdx.x;   // 0..32767
    int q = t & 3;
    int ch = t >> 2;                                 // 0..8191
    int b = ch >> 11, d = ch & (DI - 1);
    float Ar[4];
    #pragma unroll
    for (int s = 0; s < 4; s++) Ar[s] = -__expf(Alog[d * DS + q * 4 + s]);
    float h[4] = {0.f, 0.f, 0.f, 0.f};
    float Dsk = Dskip[d];
    const float* dbcB = g_dbc + (size_t)(b * L) * DBC + DTR + q * 4;
    size_t base = (size_t)(b * L) * DI + d;
    size_t zb   = (size_t)(b * L) * (2 * DI) + DI + d;
    #pragma unroll 4
    for (int l = 0; l < L; l++) {
        float delta = g_delta[base];
        float u     = g_xc[base];
        float4 Bv = *(const float4*)(dbcB + (size_t)l * DBC);
        float4 Cv = *(const float4*)(dbcB + (size_t)l * DBC + DS);
        float du = delta * u;
        float y = 0.f;
        float dA0 = __expf(delta * Ar[0]);
        float dA1 = __expf(delta * Ar[1]);
        float dA2 = __expf(delta * Ar[2]);
        float dA3 = __expf(delta * Ar[3]);
        h[0] = fmaf(dA0, h[0], du * Bv.x); y = fmaf(h[0], Cv.x, y);
        h[1] = fmaf(dA1, h[1], du * Bv.y); y = fmaf(h[1], Cv.y, y);
        h[2] = fmaf(dA2, h[2], du * Bv.z); y = fmaf(h[2], Cv.z, y);
        h[3] = fmaf(dA3, h[3], du * Bv.w); y = fmaf(h[3], Cv.w, y);
        y += __shfl_xor_sync(0xffffffffu, y, 1);
        y += __shfl_xor_sync(0xffffffffu, y, 2);
        if (q == 0) {
            float z = g_xz[zb];
            float yy = y + u * Dsk;
            float sig = 1.f / (1.f + __expf(-z));
            g_ymulh[base] = __float2bfloat16_rn(yy * (z * sig));
        }
        base += DI;
        zb   += 2 * DI;
    }
}

// ---------------- bf16 mma.sync GEMM, cp.async 3-stage pipeline + ldmatrix ----------
// C[M,N](fp32) = A[M,K](bf16) * Bt[N,K](bf16)^T.  CTA tile 128x128, BK=32.
// smem per stage: A 128 rows x 80B (64B data + 16B pad), B same.
// Fragments via ldmatrix.x4 (rows at 80B stride are bank-conflict-free).
// EPI 0: plain   EPI 2: res + gate*acc
template <int EPI>
__global__ __launch_bounds__(256, 2)
void gemm_bf16(int K, int lda, int ldb, int ldc,
               const __nv_bfloat16* __restrict__ A, const __nv_bfloat16* __restrict__ Bt,
               float* __restrict__ C,
               const float* __restrict__ res) {
    extern __shared__ char smc[];             // 3 stages x 20480 B (A|B)
    const int tid = threadIdx.x;
    const int wid = tid >> 5, lane = tid & 31;
    const int g = lane >> 2, t4 = lane & 3;
    const int wm = wid & 1, wn = wid >> 1;
    const int rowBase = blockIdx.y * 128, colBase = blockIdx.x * 128;
    const __nv_bfloat16* Ab = A  + (size_t)rowBase * lda;
    const __nv_bfloat16* Bp = Bt + (size_t)colBase * ldb;
    const uint32_t smemB = smem_u32(smc);

    // per-lane ldmatrix row/col offsets (within a stage's A or B block)
    const uint32_t aOff = (uint32_t)((wm * 64 + (lane & 15)) * 80 + ((lane >> 4) << 4));
    const uint32_t bOff = (uint32_t)((wn * 32 + ((lane >> 4) << 3) + (lane & 7)) * 80
                                     + (((lane >> 3) & 1) << 4));

    float acc[4][4][4];
    #pragma unroll
    for (int m = 0; m < 4; m++)
        #pragma unroll
        for (int n = 0; n < 4; n++)
            #pragma unroll
            for (int e = 0; e < 4; e++) acc[m][n][e] = 0.f;

    auto issue_stage = [&](int s, int k0) {
        uint32_t sb = smemB + (uint32_t)s * 20480u;
        #pragma unroll
        for (int i = 0; i < 2; i++) {
            int idx = tid + i * 256;
            int r = idx >> 2, ch = idx & 3;
            uint32_t doff = (uint32_t)(r * 80 + ch * 16);
            cp_async16(sb + doff, Ab + (size_t)r * lda + k0 + ch * 8);
            cp_async16(sb + 10240u + doff, Bp + (size_t)r * ldb + k0 + ch * 8);
        }
        CP_COMMIT();
    };

    const int nk = K >> 5;
    issue_stage(0, 0);
    issue_stage(1, 32);

    for (int k = 0; k < nk; k++) {
        CP_WAIT1();
        __syncthreads();
        if (k + 2 < nk) issue_stage((k + 2) % 3, (k + 2) * 32);
        else CP_COMMIT();

        const uint32_t sA = smemB + (uint32_t)((k % 3) * 20480);
        const uint32_t sB = sA + 10240u;
        #pragma unroll
        for (int s = 0; s < 2; s++) {          // two k16 steps per BK=32
            uint32_t af[4][4], bf[4][2];
            #pragma unroll
            for (int m = 0; m < 4; m++)
                ldsm_x4(af[m], sA + aOff + (uint32_t)(m * 16 * 80 + s * 32));
            #pragma unroll
            for (int p = 0; p < 2; p++) {
                uint32_t rb[4];
                ldsm_x4(rb, sB + bOff + (uint32_t)(p * 16 * 80 + s * 32));
                bf[2 * p + 0][0] = rb[0];
                bf[2 * p + 0][1] = rb[1];
                bf[2 * p + 1][0] = rb[2];
                bf[2 * p + 1][1] = rb[3];
            }
            #pragma unroll
            for (int m = 0; m < 4; m++)
                #pragma unroll
                for (int n = 0; n < 4; n++)
                    mma_bf16(acc[m][n], af[m], bf[n]);
        }
        __syncthreads();
    }

    // epilogue: c0,c1 at (row g, cols 2t4,2t4+1); c2,c3 at row g+8
    #pragma unroll
    for (int m = 0; m < 4; m++) {
        int r0 = rowBase + wm * 64 + m * 16 + g;
        #pragma unroll
        for (int n = 0; n < 4; n++) {
            int col = colBase + wn * 32 + n * 8 + 2 * t4;
            #pragma unroll
            for (int h = 0; h < 2; h++) {
                int r = r0 + h * 8;
                float e0 = acc[m][n][2 * h + 0];
                float e1 = acc[m][n][2 * h + 1];
                if (EPI == 2) {
                    float2 gp = *(const float2*)(g_mod + (r >> 11) * 3 * DM + 2 * DM + col);
                    float2 rp = *(const float2*)(res + (size_t)r * ldc + col);
                    e0 = rp.x + gp.x * e0;
                    e1 = rp.y + gp.y * e1;
                }
                float2 v2;
                v2.x = e0;
                v2.y = e1;
                *(float2*)(C + (size_t)r * ldc + col) = v2;
            }
        }
    }
}

// ---------------- tf32 mma.sync GEMM (fp32 in), kept for delta GEMM ----------------
// EPI 1: softplus(acc + bias[n])
template <int EPI>
__global__ __launch_bounds__(256, 2)
void gemm_mma(int K, int lda, int ldb, int ldc,
              const float* __restrict__ A, const float* __restrict__ Bt,
              float* __restrict__ C,
              const float* __restrict__ bias) {
    extern __shared__ float smem[];           // 3 stages x 8192 floats (A|B)
    const int tid = threadIdx.x;
    const int wid = tid >> 5, lane = tid & 31;
    const int g = lane >> 2, t4 = lane & 3;
    const int wm = wid & 1, wn = wid >> 1;
    const int rowBase = blockIdx.y * 128, colBase = blockIdx.x * 128;
    const float* Ab = A  + (size_t)rowBase * lda;
    const float* Bp = Bt + (size_t)colBase * ldb;
    const uint32_t smemB = smem_u32(smem);

    float acc[4][4][4];
    #pragma unroll
    for (int m = 0; m < 4; m++)
        #pragma unroll
        for (int n = 0; n < 4; n++)
            #pragma unroll
            for (int e = 0; e < 4; e++) acc[m][n][e] = 0.f;

    auto issue_stage = [&](int s, int k0) {
        uint32_t sb = smemB + (uint32_t)s * 8192u * 4u;
        #pragma unroll
        for (int i = 0; i < 4; i++) {
            int idx = tid + i * 256;
            int r = idx >> 3, cch = idx & 7;
            uint32_t doff = ((uint32_t)(r * 32 + ((cch ^ (r & 7)) << 2))) * 4u;
            cp_async16(sb + doff, Ab + (size_t)r * lda + k0 + cch * 4);
            cp_async16(sb + 16384u + doff, Bp + (size_t)r * ldb + k0 + cch * 4);
        }
        CP_COMMIT();
    };

    const int nk = K >> 5;
    issue_stage(0, 0);
    issue_stage(1, 32);

    for (int k = 0; k < nk; k++) {
        CP_WAIT1();
        __syncthreads();
        if (k + 2 < nk) issue_stage((k + 2) % 3, (k + 2) * 32);
        else CP_COMMIT();

        const float* sA = smem + (k % 3) * 8192;
        const float* sB = sA + 4096;
        const int aR = wm * 64 + g;
        const int bR = wn * 32 + g;
        #pragma unroll
        for (int kk = 0; kk < 4; kk++) {
            const int c0 = (((kk * 2 + 0) ^ g) << 2) + t4;
            const int c1 = (((kk * 2 + 1) ^ g) << 2) + t4;
            uint32_t af[4][4], bf[4][2];
            #pragma unroll
            for (int m = 0; m < 4; m++) {
                const float* p = sA + (aR + m * 16) * 32;
                af[m][0] = __float_as_uint(p[c0]);
                af[m][1] = __float_as_uint(p[8 * 32 + c0]);
                af[m][2] = __float_as_uint(p[c1]);
                af[m][3] = __float_as_uint(p[8 * 32 + c1]);
            }
            #pragma unroll
            for (int n = 0; n < 4; n++) {
                const float* p = sB + (bR + n * 8) * 32;
                bf[n][0] = __float_as_uint(p[c0]);
                bf[n][1] = __float_as_uint(p[c1]);
            }
            #pragma unroll
            for (int m = 0; m < 4; m++)
                #pragma unroll
                for (int n = 0; n < 4; n++)
                    mma_tf32(acc[m][n], af[m], bf[n]);
        }
        __syncthreads();
    }

    #pragma unroll
    for (int m = 0; m < 4; m++) {
        int r0 = rowBase + wm * 64 + m * 16 + g;
        #pragma unroll
        for (int n = 0; n < 4; n++) {
            int col = colBase + wn * 32 + n * 8 + 2 * t4;
            #pragma unroll
            for (int h = 0; h < 2; h++) {
                int r = r0 + h * 8;
                float e0 = acc[m][n][2 * h + 0];
                float e1 = acc[m][n][2 * h + 1];
                if (EPI == 1) {
                    float2 bb = *(const float2*)(bias + col);
                    e0 += bb.x;
                    e1 += bb.y;
                    e0 = (e0 > 20.f) ? e0 : log1pf(__expf(e0));
                    e1 = (e1 > 20.f) ? e1 : log1pf(__expf(e1));
                }
                float2 v2;
                v2.x = e0;
                v2.y = e1;
                *(float2*)(C + (size_t)r * ldc + col) = v2;
            }
        }
    }
}

// ---------------- fp32 SGEMM kept for the skinny N=96 projection ----------------
template <int BM, int BN, int BK, int TM, int TN>
__global__ __launch_bounds__((BM / TM) * (BN / TN))
void sgemm(int M, int N, int K, int lda, int ldb, int ldc,
           const float* __restrict__ A, const float* __restrict__ B,
           float* __restrict__ C) {
    constexpr int THREADS = (BM / TM) * (BN / TN);
    __shared__ float As[BK][BM];
    __shared__ float Bs[BK][BN];
    const int tid = threadIdx.x;
    const int tx = tid % (BN / TN);
    const int ty = tid / (BN / TN);
    const int rowBase = blockIdx.y * BM;
    const int colBase = blockIdx.x * BN;
    const float* Ablk = A + (size_t)rowBase * lda;
    const float* Bblk = B + colBase;
    float acc[TM][TN];
    #pragma unroll
    for (int i = 0; i < TM; i++)
        #pragma unroll
        for (int j = 0; j < TN; j++) acc[i][j] = 0.f;

    for (int k0 = 0; k0 < K; k0 += BK) {
        #pragma unroll
        for (int i = tid; i < BM * BK / 4; i += THREADS) {
            int m  = i / (BK / 4);
            int kk = (i % (BK / 4)) * 4;
            float4 v = *(const float4*)(Ablk + (size_t)m * lda + k0 + kk);
            As[kk + 0][m] = v.x;
            As[kk + 1][m] = v.y;
            As[kk + 2][m] = v.z;
            As[kk + 3][m] = v.w;
        }
        #pragma unroll
        for (int i = tid; i < BK * BN / 4; i += THREADS) {
            int kk = i / (BN / 4);
            int n  = (i % (BN / 4)) * 4;
            *(float4*)(&Bs[kk][n]) = *(const float4*)(Bblk + (size_t)(k0 + kk) * ldb + n);
        }
        __syncthreads();
        #pragma unroll
        for (int kk = 0; kk < BK; kk++) {
            float rav[TM], rbv[TN];
            #pragma unroll
            for (int i = 0; i < TM; i++) rav[i] = As[kk][ty * TM + i];
            #pragma unroll
            for (int j = 0; j < TN; j++) rbv[j] = Bs[kk][tx * TN + j];
            #pragma unroll
            for (int i = 0; i < TM; i++)
                #pragma unroll
                for (int j = 0; j < TN; j++)
                    acc[i][j] = fmaf(rav[i], rbv[j], acc[i][j]);
        }
        __syncthreads();
    }
    #pragma unroll
    for (int i = 0; i < TM; i++) {
        int r = rowBase + ty * TM + i;
        #pragma unroll
        for (int j = 0; j < TN; j++) {
            int n = colBase + tx * TN + j;
            C[(size_t)r * ldc + n] = acc[i][j];
        }
    }
}

// ---------------- launch ----------------
extern "C" void kernel_launch(void* const* d_in, const int* in_sizes, int n_in,
                              void* d_out, int out_size) {
    const float* x      = (const float*)d_in[0];
    const float* c      = (const float*)d_in[1];
    const float* W_in   = (const float*)d_in[2];
    const float* conv_w = (const float*)d_in[3];
    const float* conv_b = (const float*)d_in[4];
    const float* W_xp   = (const float*)d_in[5];
    const float* W_dt   = (const float*)d_in[6];
    const float* b_dt   = (const float*)d_in[7];
    const float* A_log  = (const float*)d_in[8];
    const float* D_skip = (const float*)d_in[9];
    const float* W_out  = (const float*)d_in[10];
    const float* W_ada  = (const float*)d_in[11];
    const float* b_ada  = (const float*)d_in[12];
    float* out = (float*)d_out;

    float *p_xz, *p_xc, *p_dbc, *p_delta, *p_WdtT;
    __nv_bfloat16 *p_hh, *p_ymulh, *p_WinTh, *p_WoutTh;
    cudaGetSymbolAddress((void**)&p_hh,     g_hh);
    cudaGetSymbolAddress((void**)&p_xz,     g_xz);
    cudaGetSymbolAddress((void**)&p_xc,     g_xc);
    cudaGetSymbolAddress((void**)&p_dbc,    g_dbc);
    cudaGetSymbolAddress((void**)&p_delta,  g_delta);
    cudaGetSymbolAddress((void**)&p_ymulh,  g_ymulh);
    cudaGetSymbolAddress((void**)&p_WinTh,  g_WinTh);
    cudaGetSymbolAddress((void**)&p_WdtT,   g_WdtT);
    cudaGetSymbolAddress((void**)&p_WoutTh, g_WoutTh);

    constexpr int SMEM_TF32 = 3 * 8192 * sizeof(float);   // 96 KB
    constexpr int SMEM_BF16 = 3 * 20480;                  // 60 KB
    cudaFuncSetAttribute(gemm_bf16<0>, cudaFuncAttributeMaxDynamicSharedMemorySize, SMEM_BF16);
    cudaFuncSetAttribute(gemm_bf16<2>, cudaFuncAttributeMaxDynamicSharedMemorySize, SMEM_BF16);
    cudaFuncSetAttribute(gemm_mma<1>,  cudaFuncAttributeMaxDynamicSharedMemorySize, SMEM_TF32);

    // launch index 3 is the ncu capture target -> place GEMM1 there
    // 0) fused silu+ada modulation
    k_ada<<<dim3(3 * DM / 256, Bb), 256>>>(c, W_ada, b_ada);
    // 1) LayerNorm + scale/shift -> bf16
    k_ln<<<ROWS, 256>>>(x);
    // 2) W_in transpose -> bf16 [N][K]
    k_tr_bf<<<dim3(2 * DI / 32, DM / 32), dim3(32, 8)>>>(W_in, p_WinTh, DM, 2 * DI);
    // 3) GEMM1 (bf16 mma): h @ W_in -> xz   [8192 x 4096, K=1024]   << PROFILED
    gemm_bf16<0><<<dim3(2 * DI / 128, ROWS / 128), 256, SMEM_BF16>>>(
        DM, DM, DM, 2 * DI, p_hh, p_WinTh, p_xz, nullptr);
    // 4) depthwise causal conv + silu -> xc
    k_conv<<<(ROWS * DI) / 256, 256>>>(conv_w, conv_b);
    // 5) W_dt transpose
    k_tr<<<dim3(DI / 32, DTR / 32), dim3(32, 8)>>>(W_dt, p_WdtT, DTR, DI);
    // 6) GEMM2 (fp32, skinny): xc @ W_xproj -> dbc   [8192 x 96, K=2048]
    sgemm<64, 96, 16, 4, 6><<<dim3(1, ROWS / 64), 256>>>(
        ROWS, DBC, DI, DI, DBC, DBC, p_xc, W_xp, p_dbc);
    // 7) delta GEMM (tf32 mma): dbc[:, :64] @ W_dt + b_dt, softplus -> delta
    gemm_mma<1><<<dim3(DI / 128, ROWS / 128), 256, SMEM_TF32>>>(
        DTR, DBC, DTR, DI, p_dbc, p_WdtT, p_delta, b_dt);
    // 8) selective scan (4-way state split) + skip + silu(z) gate -> ymul (bf16)
    k_scan4<<<(4 * ROWS) / 256, 256>>>(A_log, D_skip);
    // 9) W_out transpose -> bf16
    k_tr_bf<<<dim3(DM / 32, DI / 32), dim3(32, 8)>>>(W_out, p_WoutTh, DI, DM);
    // 10) GEMM3 (bf16 mma): ymul @ W_out, fused residual + gate -> out
    gemm_bf16<2><<<dim3(DM / 128, ROWS / 128), 256, SMEM_BF16>>>(
        DI, DI, DI, DM, p_ymulh, p_WoutTh, out, x);
}

// round 15
// speedup vs baseline: 1.0323x; 1.0323x over previous
#include <cuda_runtime.h>
#include <cuda_bf16.h>
#include <cstdint>
#include <cstddef>

// ---------------- problem constants ----------------
static constexpr int Bb  = 4;
static constexpr int L   = 2048;
static constexpr int DM  = 1024;          // d_model
static constexpr int DI  = 2048;          // d_inner
static constexpr int DS  = 16;            // d_state
static constexpr int DTR = 64;            // dt_rank
static constexpr int ROWS = Bb * L;       // 8192
static constexpr int DBCP = 128;          // padded dt|B|C row (96 -> 128)

// ---------------- scratch (device globals, no allocations) ----------------
__device__ float g_mod[Bb * 3 * DM];                      // scale|shift|gate
__device__ __nv_bfloat16 g_hh[(size_t)ROWS * DM];         // LN-modulated input
__device__ __nv_bfloat16 g_xzh[(size_t)ROWS * 2 * DI];    // x@W_in (xm | z) bf16
__device__ __nv_bfloat16 g_xch[(size_t)ROWS * DI];        // conv+silu bf16
__device__ float g_dbc[(size_t)ROWS * DBCP];              // dt | B | C | pad
__device__ float g_delta[(size_t)ROWS * DI];              // softplus(dt@W_dt+b)
__device__ __nv_bfloat16 g_ymulh[(size_t)ROWS * DI];      // (scan+u*D)*silu(z)
__device__ __nv_bfloat16 g_WinTh[(size_t)(2 * DI) * DM];  // W_in^T  bf16 [4096][1024]
__device__ __nv_bfloat16 g_WxpTh[(size_t)DBCP * DI];      // W_xp^T  bf16 [128][2048] (pad rows 96..127 = 0)
__device__ float g_WdtT[(size_t)DI * DTR];                // W_dt^T  fp32 [2048][64]
__device__ __nv_bfloat16 g_WoutTh[(size_t)DM * DI];       // W_out^T bf16 [1024][2048]

// ---------------- helpers ----------------
__device__ __forceinline__ uint32_t smem_u32(const void* p) {
    uint32_t a;
    asm("{ .reg .u64 t; cvta.to.shared.u64 t, %1; cvt.u32.u64 %0, t; }" : "=r"(a) : "l"(p));
    return a;
}
__device__ __forceinline__ void cp_async16(uint32_t dst, const void* src) {
    asm volatile("cp.async.cg.shared.global [%0], [%1], 16;"
                 :: "r"(dst), "l"(__cvta_generic_to_global(src)));
}
#define CP_COMMIT() asm volatile("cp.async.commit_group;" ::: "memory")
#define CP_WAIT1()  asm volatile("cp.async.wait_group 1;" ::: "memory")

__device__ __forceinline__ void mma_tf32(float* c, const uint32_t* a, const uint32_t* b) {
    asm volatile(
        "mma.sync.aligned.m16n8k8.row.col.f32.tf32.tf32.f32 "
        "{%0,%1,%2,%3}, {%4,%5,%6,%7}, {%8,%9}, {%0,%1,%2,%3};"
        : "+f"(c[0]), "+f"(c[1]), "+f"(c[2]), "+f"(c[3])
        : "r"(a[0]), "r"(a[1]), "r"(a[2]), "r"(a[3]), "r"(b[0]), "r"(b[1]));
}
__device__ __forceinline__ void mma_bf16(float* c, const uint32_t* a, const uint32_t* b) {
    asm volatile(
        "mma.sync.aligned.m16n8k16.row.col.f32.bf16.bf16.f32 "
        "{%0,%1,%2,%3}, {%4,%5,%6,%7}, {%8,%9}, {%0,%1,%2,%3};"
        : "+f"(c[0]), "+f"(c[1]), "+f"(c[2]), "+f"(c[3])
        : "r"(a[0]), "r"(a[1]), "r"(a[2]), "r"(a[3]), "r"(b[0]), "r"(b[1]));
}
__device__ __forceinline__ void ldsm_x4(uint32_t* r, uint32_t addr) {
    asm volatile("ldmatrix.sync.aligned.m8n8.x4.shared.b16 {%0,%1,%2,%3}, [%4];"
                 : "=r"(r[0]), "=r"(r[1]), "=r"(r[2]), "=r"(r[3]) : "r"(addr));
}

// ---------------- k_pre: fused ada + all weight transposes ----------------
// blocks [0,48): ada.  [48,4144): W_in^T bf16.  [4144,4400): W_xp^T bf16 padded.
// [4400,4528): W_dt^T fp32.  [4528,6576): W_out^T bf16.   block = (32,8)
__global__ void k_pre(const float* __restrict__ c,  const float* __restrict__ Wada,
                      const float* __restrict__ bada,
                      const float* __restrict__ Win, const float* __restrict__ Wxp,
                      const float* __restrict__ Wdt, const float* __restrict__ Wout) {
    int bx = blockIdx.x;
    int tx = threadIdx.x, ty = threadIdx.y;
    __shared__ float t[32][33];
    if (bx < 48) {
        __shared__ float sc[DM];
        int tid = ty * 32 + tx;
        int b = bx / 12;
        int j = (bx % 12) * 256 + tid;
        for (int k = tid; k < DM; k += 256) {
            float v = c[b * DM + k];
            sc[k] = v / (1.f + __expf(-v));
        }
        __syncthreads();
        float a[8];
        #pragma unroll
        for (int i = 0; i < 8; i++) a[i] = 0.f;
        for (int k = 0; k < DM; k += 8) {
            #pragma unroll
            for (int i = 0; i < 8; i++)
                a[i] += sc[k + i] * Wada[(size_t)(k + i) * (3 * DM) + j];
        }
        float s = 0.f;
        #pragma unroll
        for (int i = 0; i < 8; i++) s += a[i];
        g_mod[b * 3 * DM + j] = bada[j] + s;
        return;
    }
    bx -= 48;
    if (bx < 4096) {                  // W_in [1024][4096] -> [4096][1024] bf16
        int c0 = (bx & 127) * 32, r0 = (bx >> 7) * 32;
        #pragma unroll
        for (int j = 0; j < 4; j++)
            t[ty + 8 * j][tx] = Win[(size_t)(r0 + ty + 8 * j) * (2 * DI) + c0 + tx];
        __syncthreads();
        #pragma unroll
        for (int j = 0; j < 4; j++)
            g_WinTh[(size_t)(c0 + ty + 8 * j) * DM + r0 + tx] =
                __float2bfloat16_rn(t[tx][ty + 8 * j]);
        return;
    }
    bx -= 4096;
    if (bx < 256) {                   // W_xp [2048][96] -> [128][2048] bf16, rows 96..127 = 0
        int dty = bx & 3, dtx = bx >> 2;
        int dr0 = dty * 32, dc0 = dtx * 32;
        if (dty == 3) {
            #pragma unroll
            for (int j = 0; j < 4; j++)
                g_WxpTh[(size_t)(dr0 + ty + 8 * j) * DI + dc0 + tx] = __float2bfloat16_rn(0.f);
            return;
        }
        #pragma unroll
        for (int j = 0; j < 4; j++)
            t[ty + 8 * j][tx] = Wxp[(size_t)(dc0 + ty + 8 * j) * 96 + dr0 + tx];
        __syncthreads();
        #pragma unroll
        for (int j = 0; j < 4; j++)
            g_WxpTh[(size_t)(dr0 + ty + 8 * j) * DI + dc0 + tx] =
                __float2bfloat16_rn(t[tx][ty + 8 * j]);
        return;
    }
    bx -= 256;
    if (bx < 128) {                   // W_dt [64][2048] -> [2048][64] fp32
        int c0 = (bx & 63) * 32, r0 = (bx >> 6) * 32;
        #pragma unroll
        for (int j = 0; j < 4; j++)
            t[ty + 8 * j][tx] = Wdt[(size_t)(r0 + ty + 8 * j) * DI + c0 + tx];
        __syncthreads();
        #pragma unroll
        for (int j = 0; j < 4; j++)
            g_WdtT[(size_t)(c0 + ty + 8 * j) * DTR + r0 + tx] = t[tx][ty + 8 * j];
        return;
    }
    bx -= 128;
    {                                 // W_out [2048][1024] -> [1024][2048] bf16
        int c0 = (bx & 31) * 32, r0 = (bx >> 5) * 32;
        #pragma unroll
        for (int j = 0; j < 4; j++)
            t[ty + 8 * j][tx] = Wout[(size_t)(r0 + ty + 8 * j) * DM + c0 + tx];
        __syncthreads();
        #pragma unroll
        for (int j = 0; j < 4; j++)
            g_WoutTh[(size_t)(c0 + ty + 8 * j) * DI + r0 + tx] =
                __float2bfloat16_rn(t[tx][ty + 8 * j]);
    }
}

// LayerNorm + (1+scale)*xn + shift -> g_hh (bf16)
__global__ void k_ln(const float* __restrict__ x) {
    int row = blockIdx.x;
    int b = row >> 11;
    const float4* xr = (const float4*)(x + (size_t)row * DM);
    float4 v = xr[threadIdx.x];
    float s = v.x + v.y + v.z + v.w;
    float q = v.x * v.x + v.y * v.y + v.z * v.z + v.w * v.w;
    #pragma unroll
    for (int o = 16; o; o >>= 1) {
        s += __shfl_xor_sync(0xffffffffu, s, o);
        q += __shfl_xor_sync(0xffffffffu, q, o);
    }
    __shared__ float ss[8], sq[8];
    int w = threadIdx.x >> 5;
    if ((threadIdx.x & 31) == 0) { ss[w] = s; sq[w] = q; }
    __syncthreads();
    s = 0.f; q = 0.f;
    #pragma unroll
    for (int i = 0; i < 8; i++) { s += ss[i]; q += sq[i]; }
    float mean = s * (1.f / DM);
    float var  = q * (1.f / DM) - mean * mean;
    float rstd = rsqrtf(var + 1e-6f);
    int col = threadIdx.x * 4;
    float4 sc4 = *(const float4*)(g_mod + b * 3 * DM + col);
    float4 sh4 = *(const float4*)(g_mod + b * 3 * DM + DM + col);
    float o0 = (v.x - mean) * rstd * (1.f + sc4.x) + sh4.x;
    float o1 = (v.y - mean) * rstd * (1.f + sc4.y) + sh4.y;
    float o2 = (v.z - mean) * rstd * (1.f + sc4.z) + sh4.z;
    float o3 = (v.w - mean) * rstd * (1.f + sc4.w) + sh4.w;
    __nv_bfloat162 h0 = __floats2bfloat162_rn(o0, o1);
    __nv_bfloat162 h1 = __floats2bfloat162_rn(o2, o3);
    uint2 u;
    u.x = *(uint32_t*)&h0;
    u.y = *(uint32_t*)&h1;
    *(uint2*)(g_hh + (size_t)row * DM + col) = u;
}

// depthwise causal conv (kernel 4) + silu on bf16 xz -> bf16 xc. 2 channels/thread.
__global__ void k_conv(const float* __restrict__ cw, const float* __restrict__ cb) {
    int i = blockIdx.x * blockDim.x + threadIdx.x;    // 0 .. ROWS*DI/2-1
    int d2 = i & 1023;
    int row = i >> 10;
    int l = row & (L - 1);
    int d = d2 << 1;
    const __nv_bfloat162* xm = (const __nv_bfloat162*)g_xzh;   // row stride = 2048 pairs
    size_t rb = (size_t)row * 2048 + d2;
    float4 wa = *(const float4*)(cw + 4 * d);
    float4 wb = *(const float4*)(cw + 4 * d + 4);
    float2 c2 = *(const float2*)(cb + d);
    float2 x0 = __bfloat1622float2(xm[rb]);
    float ax = fmaf(x0.x, wa.w, c2.x);
    float ay = fmaf(x0.y, wb.w, c2.y);
    if (l >= 1) { float2 x1 = __bfloat1622float2(xm[rb - 2048]);
                  ax = fmaf(x1.x, wa.z, ax); ay = fmaf(x1.y, wb.z, ay); }
    if (l >= 2) { float2 x1 = __bfloat1622float2(xm[rb - 2 * 2048]);
                  ax = fmaf(x1.x, wa.y, ax); ay = fmaf(x1.y, wb.y, ay); }
    if (l >= 3) { float2 x1 = __bfloat1622float2(xm[rb - 3 * 2048]);
                  ax = fmaf(x1.x, wa.x, ax); ay = fmaf(x1.y, wb.x, ay); }
    float sx = ax / (1.f + __expf(-ax));
    float sy = ay / (1.f + __expf(-ay));
    ((__nv_bfloat162*)g_xch)[(size_t)row * 1024 + d2] = __floats2bfloat162_rn(sx, sy);
}

// selective scan: 4 threads per (b,d) channel, 4 states each. bf16 in/out.
__global__ void k_scan4(const float* __restrict__ Alog, const float* __restrict__ Dskip) {
    int t = blockIdx.x * blockDim.x + threadIdx.x;   // 0..32767
    int q = t & 3;
    int ch = t >> 2;                                 // 0..8191
    int b = ch >> 11, d = ch & (DI - 1);
    float Ar[4];
    #pragma unroll
    for (int s = 0; s < 4; s++) Ar[s] = -__expf(Alog[d * DS + q * 4 + s]);
    float h[4] = {0.f, 0.f, 0.f, 0.f};
    float Dsk = Dskip[d];
    const float* dbcB = g_dbc + (size_t)(b * L) * DBCP + DTR + q * 4;
    size_t base = (size_t)(b * L) * DI + d;
    size_t zb   = (size_t)(b * L) * (2 * DI) + DI + d;
    #pragma unroll 4
    for (int l = 0; l < L; l++) {
        float delta = g_delta[base];
        float u     = __bfloat162float(g_xch[base]);
        float4 Bv = *(const float4*)(dbcB + (size_t)l * DBCP);
        float4 Cv = *(const float4*)(dbcB + (size_t)l * DBCP + DS);
        float du = delta * u;
        float y = 0.f;
        float dA0 = __expf(delta * Ar[0]);
        float dA1 = __expf(delta * Ar[1]);
        float dA2 = __expf(delta * Ar[2]);
        float dA3 = __expf(delta * Ar[3]);
        h[0] = fmaf(dA0, h[0], du * Bv.x); y = fmaf(h[0], Cv.x, y);
        h[1] = fmaf(dA1, h[1], du * Bv.y); y = fmaf(h[1], Cv.y, y);
        h[2] = fmaf(dA2, h[2], du * Bv.z); y = fmaf(h[2], Cv.z, y);
        h[3] = fmaf(dA3, h[3], du * Bv.w); y = fmaf(h[3], Cv.w, y);
        y += __shfl_xor_sync(0xffffffffu, y, 1);
        y += __shfl_xor_sync(0xffffffffu, y, 2);
        if (q == 0) {
            float z = __bfloat162float(g_xzh[zb]);
            float yy = y + u * Dsk;
            float sig = 1.f / (1.f + __expf(-z));
            g_ymulh[base] = __float2bfloat16_rn(yy * (z * sig));
        }
        base += DI;
        zb   += 2 * DI;
    }
}

// ---------------- bf16 mma.sync GEMM, cp.async 3-stage pipeline + ldmatrix ----------
// C[M,N] = A[M,K](bf16) * Bt[N,K](bf16)^T.  CTA tile 128x128, BK=32.
// EPI 0: fp32 out plain   EPI 2: fp32 out res+gate*acc   EPI 3: bf16 out plain
template <int EPI>
__global__ __launch_bounds__(256, 2)
void gemm_bf16(int K, int lda, int ldb, int ldc,
               const __nv_bfloat16* __restrict__ A, const __nv_bfloat16* __restrict__ Bt,
               void* __restrict__ Cv,
               const float* __restrict__ res) {
    extern __shared__ char smc[];             // 3 stages x 20480 B (A|B)
    const int tid = threadIdx.x;
    const int wid = tid >> 5, lane = tid & 31;
    const int g = lane >> 2, t4 = lane & 3;
    const int wm = wid & 1, wn = wid >> 1;
    const int rowBase = blockIdx.y * 128, colBase = blockIdx.x * 128;
    const __nv_bfloat16* Ab = A  + (size_t)rowBase * lda;
    const __nv_bfloat16* Bp = Bt + (size_t)colBase * ldb;
    const uint32_t smemB = smem_u32(smc);

    const uint32_t aOff = (uint32_t)((wm * 64 + (lane & 15)) * 80 + ((lane >> 4) << 4));
    const uint32_t bOff = (uint32_t)((wn * 32 + ((lane >> 4) << 3) + (lane & 7)) * 80
                                     + (((lane >> 3) & 1) << 4));

    float acc[4][4][4];
    #pragma unroll
    for (int m = 0; m < 4; m++)
        #pragma unroll
        for (int n = 0; n < 4; n++)
            #pragma unroll
            for (int e = 0; e < 4; e++) acc[m][n][e] = 0.f;

    auto issue_stage = [&](int s, int k0) {
        uint32_t sb = smemB + (uint32_t)s * 20480u;
        #pragma unroll
        for (int i = 0; i < 2; i++) {
            int idx = tid + i * 256;
            int r = idx >> 2, ch = idx & 3;
            uint32_t doff = (uint32_t)(r * 80 + ch * 16);
            cp_async16(sb + doff, Ab + (size_t)r * lda + k0 + ch * 8);
            cp_async16(sb + 10240u + doff, Bp + (size_t)r * ldb + k0 + ch * 8);
        }
        CP_COMMIT();
    };

    const int nk = K >> 5;
    issue_stage(0, 0);
    issue_stage(1, 32);

    for (int k = 0; k < nk; k++) {
        CP_WAIT1();
        __syncthreads();
        if (k + 2 < nk) issue_stage((k + 2) % 3, (k + 2) * 32);
        else CP_COMMIT();

        const uint32_t sA = smemB + (uint32_t)((k % 3) * 20480);
        const uint32_t sB = sA + 10240u;
        #pragma unroll
        for (int s = 0; s < 2; s++) {
            uint32_t af[4][4], bf[4][2];
            #pragma unroll
            for (int m = 0; m < 4; m++)
                ldsm_x4(af[m], sA + aOff + (uint32_t)(m * 16 * 80 + s * 32));
            #pragma unroll
            for (int p = 0; p < 2; p++) {
                uint32_t rb[4];
                ldsm_x4(rb, sB + bOff + (uint32_t)(p * 16 * 80 + s * 32));
                bf[2 * p + 0][0] = rb[0];
                bf[2 * p + 0][1] = rb[1];
                bf[2 * p + 1][0] = rb[2];
                bf[2 * p + 1][1] = rb[3];
            }
            #pragma unroll
            for (int m = 0; m < 4; m++)
                #pragma unroll
                for (int n = 0; n < 4; n++)
                    mma_bf16(acc[m][n], af[m], bf[n]);
        }
        __syncthreads();
    }

    #pragma unroll
    for (int m = 0; m < 4; m++) {
        int r0 = rowBase + wm * 64 + m * 16 + g;
        #pragma unroll
        for (int n = 0; n < 4; n++) {
            int col = colBase + wn * 32 + n * 8 + 2 * t4;
            #pragma unroll
            for (int h = 0; h < 2; h++) {
                int r = r0 + h * 8;
                float e0 = acc[m][n][2 * h + 0];
                float e1 = acc[m][n][2 * h + 1];
                if (EPI == 2) {
                    float2 gp = *(const float2*)(g_mod + (r >> 11) * 3 * DM + 2 * DM + col);
                    float2 rp = *(const float2*)(res + (size_t)r * ldc + col);
                    e0 = rp.x + gp.x * e0;
                    e1 = rp.y + gp.y * e1;
                }
                if (EPI == 3) {
                    __nv_bfloat162 pk = __floats2bfloat162_rn(e0, e1);
                    *(__nv_bfloat162*)((__nv_bfloat16*)Cv + (size_t)r * ldc + col) = pk;
                } else {
                    float2 v2;
                    v2.x = e0;
                    v2.y = e1;
                    *(float2*)((float*)Cv + (size_t)r * ldc + col) = v2;
                }
            }
        }
    }
}

// ---------------- tf32 mma.sync GEMM (fp32 in) for delta GEMM ----------------
// EPI 1: softplus(acc + bias[n])
template <int EPI>
__global__ __launch_bounds__(256, 2)
void gemm_mma(int K, int lda, int ldb, int ldc,
              const float* __restrict__ A, const float* __restrict__ Bt,
              float* __restrict__ C,
              const float* __restrict__ bias) {
    extern __shared__ float smem[];
    const int tid = threadIdx.x;
    const int wid = tid >> 5, lane = tid & 31;
    const int g = lane >> 2, t4 = lane & 3;
    const int wm = wid & 1, wn = wid >> 1;
    const int rowBase = blockIdx.y * 128, colBase = blockIdx.x * 128;
    const float* Ab = A  + (size_t)rowBase * lda;
    const float* Bp = Bt + (size_t)colBase * ldb;
    const uint32_t smemB = smem_u32(smem);

    float acc[4][4][4];
    #pragma unroll
    for (int m = 0; m < 4; m++)
        #pragma unroll
        for (int n = 0; n < 4; n++)
            #pragma unroll
            for (int e = 0; e < 4; e++) acc[m][n][e] = 0.f;

    auto issue_stage = [&](int s, int k0) {
        uint32_t sb = smemB + (uint32_t)s * 8192u * 4u;
        #pragma unroll
        for (int i = 0; i < 4; i++) {
            int idx = tid + i * 256;
            int r = idx >> 3, cch = idx & 7;
            uint32_t doff = ((uint32_t)(r * 32 + ((cch ^ (r & 7)) << 2))) * 4u;
            cp_async16(sb + doff, Ab + (size_t)r * lda + k0 + cch * 4);
            cp_async16(sb + 16384u + doff, Bp + (size_t)r * ldb + k0 + cch * 4);
        }
        CP_COMMIT();
    };

    const int nk = K >> 5;
    issue_stage(0, 0);
    issue_stage(1, 32);

    for (int k = 0; k < nk; k++) {
        CP_WAIT1();
        __syncthreads();
        if (k + 2 < nk) issue_stage((k + 2) % 3, (k + 2) * 32);
        else CP_COMMIT();

        const float* sA = smem + (k % 3) * 8192;
        const float* sB = sA + 4096;
        const int aR = wm * 64 + g;
        const int bR = wn * 32 + g;
        #pragma unroll
        for (int kk = 0; kk < 4; kk++) {
            const int c0 = (((kk * 2 + 0) ^ g) << 2) + t4;
            const int c1 = (((kk * 2 + 1) ^ g) << 2) + t4;
            uint32_t af[4][4], bf[4][2];
            #pragma unroll
            for (int m = 0; m < 4; m++) {
                const float* p = sA + (aR + m * 16) * 32;
                af[m][0] = __float_as_uint(p[c0]);
                af[m][1] = __float_as_uint(p[8 * 32 + c0]);
                af[m][2] = __float_as_uint(p[c1]);
                af[m][3] = __float_as_uint(p[8 * 32 + c1]);
            }
            #pragma unroll
            for (int n = 0; n < 4; n++) {
                const float* p = sB + (bR + n * 8) * 32;
                bf[n][0] = __float_as_uint(p[c0]);
                bf[n][1] = __float_as_uint(p[c1]);
            }
            #pragma unroll
            for (int m = 0; m < 4; m++)
                #pragma unroll
                for (int n = 0; n < 4; n++)
                    mma_tf32(acc[m][n], af[m], bf[n]);
        }
        __syncthreads();
    }

    #pragma unroll
    for (int m = 0; m < 4; m++) {
        int r0 = rowBase + wm * 64 + m * 16 + g;
        #pragma unroll
        for (int n = 0; n < 4; n++) {
            int col = colBase + wn * 32 + n * 8 + 2 * t4;
            #pragma unroll
            for (int h = 0; h < 2; h++) {
                int r = r0 + h * 8;
                float e0 = acc[m][n][2 * h + 0];
                float e1 = acc[m][n][2 * h + 1];
                if (EPI == 1) {
                    float2 bb = *(const float2*)(bias + col);
                    e0 += bb.x;
                    e1 += bb.y;
                    e0 = (e0 > 20.f) ? e0 : log1pf(__expf(e0));
                    e1 = (e1 > 20.f) ? e1 : log1pf(__expf(e1));
                }
                float2 v2;
                v2.x = e0;
                v2.y = e1;
                *(float2*)(C + (size_t)r * ldc + col) = v2;
            }
        }
    }
}

// ---------------- launch ----------------
extern "C" void kernel_launch(void* const* d_in, const int* in_sizes, int n_in,
                              void* d_out, int out_size) {
    const float* x      = (const float*)d_in[0];
    const float* c      = (const float*)d_in[1];
    const float* W_in   = (const float*)d_in[2];
    const float* conv_w = (const float*)d_in[3];
    const float* conv_b = (const float*)d_in[4];
    const float* W_xp   = (const float*)d_in[5];
    const float* W_dt   = (const float*)d_in[6];
    const float* b_dt   = (const float*)d_in[7];
    const float* A_log  = (const float*)d_in[8];
    const float* D_skip = (const float*)d_in[9];
    const float* W_out  = (const float*)d_in[10];
    const float* W_ada  = (const float*)d_in[11];
    const float* b_ada  = (const float*)d_in[12];
    float* out = (float*)d_out;

    float *p_dbc, *p_delta, *p_WdtT;
    __nv_bfloat16 *p_hh, *p_xzh, *p_xch, *p_ymulh, *p_WinTh, *p_WxpTh, *p_WoutTh;
    cudaGetSymbolAddress((void**)&p_hh,     g_hh);
    cudaGetSymbolAddress((void**)&p_xzh,    g_xzh);
    cudaGetSymbolAddress((void**)&p_xch,    g_xch);
    cudaGetSymbolAddress((void**)&p_dbc,    g_dbc);
    cudaGetSymbolAddress((void**)&p_delta,  g_delta);
    cudaGetSymbolAddress((void**)&p_ymulh,  g_ymulh);
    cudaGetSymbolAddress((void**)&p_WinTh,  g_WinTh);
    cudaGetSymbolAddress((void**)&p_WxpTh,  g_WxpTh);
    cudaGetSymbolAddress((void**)&p_WdtT,   g_WdtT);
    cudaGetSymbolAddress((void**)&p_WoutTh, g_WoutTh);

    constexpr int SMEM_TF32 = 3 * 8192 * sizeof(float);   // 96 KB
    constexpr int SMEM_BF16 = 3 * 20480;                  // 60 KB
    cudaFuncSetAttribute(gemm_bf16<0>, cudaFuncAttributeMaxDynamicSharedMemorySize, SMEM_BF16);
    cudaFuncSetAttribute(gemm_bf16<2>, cudaFuncAttributeMaxDynamicSharedMemorySize, SMEM_BF16);
    cudaFuncSetAttribute(gemm_bf16<3>, cudaFuncAttributeMaxDynamicSharedMemorySize, SMEM_BF16);
    cudaFuncSetAttribute(gemm_mma<1>,  cudaFuncAttributeMaxDynamicSharedMemorySize, SMEM_TF32);

    // 0) fused ada + all weight transposes
    k_pre<<<6576, dim3(32, 8)>>>(c, W_ada, b_ada, W_in, W_xp, W_dt, W_out);
    // 1) LayerNorm + scale/shift -> bf16
    k_ln<<<ROWS, 256>>>(x);
    // 2) GEMM1 (bf16): h @ W_in -> xz (bf16)   [8192 x 4096, K=1024]
    gemm_bf16<3><<<dim3(2 * DI / 128, ROWS / 128), 256, SMEM_BF16>>>(
        DM, DM, DM, 2 * DI, p_hh, p_WinTh, p_xzh, nullptr);
    // 3) conv + silu (bf16 -> bf16)                                << PROFILED
    k_conv<<<(ROWS * DI / 2) / 256, 256>>>(conv_w, conv_b);
    // 4) GEMM2 (bf16): xc @ W_xproj(pad 128) -> dbc fp32 [8192 x 128, K=2048]
    gemm_bf16<0><<<dim3(1, ROWS / 128), 256, SMEM_BF16>>>(
        DI, DI, DI, DBCP, p_xch, p_WxpTh, p_dbc, nullptr);
    // 5) delta GEMM (tf32): dbc[:, :64] @ W_dt + b_dt, softplus -> delta fp32
    gemm_mma<1><<<dim3(DI / 128, ROWS / 128), 256, SMEM_TF32>>>(
        DTR, DBCP, DTR, DI, p_dbc, p_WdtT, p_delta, b_dt);
    // 6) selective scan + skip + silu(z) gate -> ymul (bf16)
    k_scan4<<<(4 * ROWS) / 256, 256>>>(A_log, D_skip);
    // 7) GEMM3 (bf16): ymul @ W_out, fused residual + gate -> out
    gemm_bf16<2><<<dim3(DM / 128, ROWS / 128), 256, SMEM_BF16>>>(
        DI, DI, DI, DM, p_ymulh, p_WoutTh, out, x);
}

// round 16
// speedup vs baseline: 1.9333x; 1.8729x over previous
#include <cuda_runtime.h>
#include <cuda_bf16.h>
#include <cstdint>
#include <cstddef>

// ---------------- problem constants ----------------
static constexpr int Bb  = 4;
static constexpr int L   = 2048;
static constexpr int DM  = 1024;          // d_model
static constexpr int DI  = 2048;          // d_inner
static constexpr int DS  = 16;            // d_state
static constexpr int DTR = 64;            // dt_rank
static constexpr int ROWS = Bb * L;       // 8192
static constexpr int DBCP = 128;          // padded dt|B|C row (96 -> 128)

// ---------------- scratch (device globals, no allocations) ----------------
__device__ float g_mod[Bb * 3 * DM];                      // scale|shift|gate
__device__ __nv_bfloat16 g_hh[(size_t)ROWS * DM];         // LN-modulated input
__device__ __nv_bfloat16 g_xzh[(size_t)ROWS * 2 * DI];    // x@W_in (xm | z) bf16
__device__ __nv_bfloat16 g_xch[(size_t)ROWS * DI];        // conv+silu bf16
__device__ float g_dbc[(size_t)ROWS * DBCP];              // dt | B | C | pad
__device__ float g_delta[(size_t)ROWS * DI];              // softplus(dt@W_dt+b)
__device__ __nv_bfloat16 g_ymulh[(size_t)ROWS * DI];      // (scan+u*D)*silu(z)
__device__ __nv_bfloat16 g_WinTh[(size_t)(2 * DI) * DM];  // W_in^T  bf16 [4096][1024]
__device__ __nv_bfloat16 g_WxpTh[(size_t)DBCP * DI];      // W_xp^T  bf16 [128][2048]
__device__ float g_WdtT[(size_t)DI * DTR];                // W_dt^T  fp32 [2048][64]
__device__ __nv_bfloat16 g_WoutTh[(size_t)DM * DI];       // W_out^T bf16 [1024][2048]

// ---------------- helpers ----------------
__device__ __forceinline__ uint32_t smem_u32(const void* p) {
    uint32_t a;
    asm("{ .reg .u64 t; cvta.to.shared.u64 t, %1; cvt.u32.u64 %0, t; }" : "=r"(a) : "l"(p));
    return a;
}
__device__ __forceinline__ void cp_async16(uint32_t dst, const void* src) {
    asm volatile("cp.async.cg.shared.global [%0], [%1], 16;"
                 :: "r"(dst), "l"(__cvta_generic_to_global(src)));
}
#define CP_COMMIT() asm volatile("cp.async.commit_group;" ::: "memory")
#define CP_WAIT1()  asm volatile("cp.async.wait_group 1;" ::: "memory")

__device__ __forceinline__ void mma_tf32(float* c, const uint32_t* a, const uint32_t* b) {
    asm volatile(
        "mma.sync.aligned.m16n8k8.row.col.f32.tf32.tf32.f32 "
        "{%0,%1,%2,%3}, {%4,%5,%6,%7}, {%8,%9}, {%0,%1,%2,%3};"
        : "+f"(c[0]), "+f"(c[1]), "+f"(c[2]), "+f"(c[3])
        : "r"(a[0]), "r"(a[1]), "r"(a[2]), "r"(a[3]), "r"(b[0]), "r"(b[1]));
}
__device__ __forceinline__ void mma_bf16(float* c, const uint32_t* a, const uint32_t* b) {
    asm volatile(
        "mma.sync.aligned.m16n8k16.row.col.f32.bf16.bf16.f32 "
        "{%0,%1,%2,%3}, {%4,%5,%6,%7}, {%8,%9}, {%0,%1,%2,%3};"
        : "+f"(c[0]), "+f"(c[1]), "+f"(c[2]), "+f"(c[3])
        : "r"(a[0]), "r"(a[1]), "r"(a[2]), "r"(a[3]), "r"(b[0]), "r"(b[1]));
}
__device__ __forceinline__ void ldsm_x4(uint32_t* r, uint32_t addr) {
    asm volatile("ldmatrix.sync.aligned.m8n8.x4.shared.b16 {%0,%1,%2,%3}, [%4];"
                 : "=r"(r[0]), "=r"(r[1]), "=r"(r[2]), "=r"(r[3]) : "r"(addr));
}

// ---------------- k_pre: fused ada + all weight transposes ----------------
__global__ void k_pre(const float* __restrict__ c,  const float* __restrict__ Wada,
                      const float* __restrict__ bada,
                      const float* __restrict__ Win, const float* __restrict__ Wxp,
                      const float* __restrict__ Wdt, const float* __restrict__ Wout) {
    int bx = blockIdx.x;
    int tx = threadIdx.x, ty = threadIdx.y;
    __shared__ float t[32][33];
    if (bx < 48) {
        __shared__ float sc[DM];
        int tid = ty * 32 + tx;
        int b = bx / 12;
        int j = (bx % 12) * 256 + tid;
        for (int k = tid; k < DM; k += 256) {
            float v = c[b * DM + k];
            sc[k] = v / (1.f + __expf(-v));
        }
        __syncthreads();
        float a[8];
        #pragma unroll
        for (int i = 0; i < 8; i++) a[i] = 0.f;
        for (int k = 0; k < DM; k += 8) {
            #pragma unroll
            for (int i = 0; i < 8; i++)
                a[i] += sc[k + i] * Wada[(size_t)(k + i) * (3 * DM) + j];
        }
        float s = 0.f;
        #pragma unroll
        for (int i = 0; i < 8; i++) s += a[i];
        g_mod[b * 3 * DM + j] = bada[j] + s;
        return;
    }
    bx -= 48;
    if (bx < 4096) {                  // W_in [1024][4096] -> [4096][1024] bf16
        int c0 = (bx & 127) * 32, r0 = (bx >> 7) * 32;
        #pragma unroll
        for (int j = 0; j < 4; j++)
            t[ty + 8 * j][tx] = Win[(size_t)(r0 + ty + 8 * j) * (2 * DI) + c0 + tx];
        __syncthreads();
        #pragma unroll
        for (int j = 0; j < 4; j++)
            g_WinTh[(size_t)(c0 + ty + 8 * j) * DM + r0 + tx] =
                __float2bfloat16_rn(t[tx][ty + 8 * j]);
        return;
    }
    bx -= 4096;
    if (bx < 256) {                   // W_xp [2048][96] -> [128][2048] bf16, rows 96..127 = 0
        int dty = bx & 3, dtx = bx >> 2;
        int dr0 = dty * 32, dc0 = dtx * 32;
        if (dty == 3) {
            #pragma unroll
            for (int j = 0; j < 4; j++)
                g_WxpTh[(size_t)(dr0 + ty + 8 * j) * DI + dc0 + tx] = __float2bfloat16_rn(0.f);
            return;
        }
        #pragma unroll
        for (int j = 0; j < 4; j++)
            t[ty + 8 * j][tx] = Wxp[(size_t)(dc0 + ty + 8 * j) * 96 + dr0 + tx];
        __syncthreads();
        #pragma unroll
        for (int j = 0; j < 4; j++)
            g_WxpTh[(size_t)(dr0 + ty + 8 * j) * DI + dc0 + tx] =
                __float2bfloat16_rn(t[tx][ty + 8 * j]);
        return;
    }
    bx -= 256;
    if (bx < 128) {                   // W_dt [64][2048] -> [2048][64] fp32
        int c0 = (bx & 63) * 32, r0 = (bx >> 6) * 32;
        #pragma unroll
        for (int j = 0; j < 4; j++)
            t[ty + 8 * j][tx] = Wdt[(size_t)(r0 + ty + 8 * j) * DI + c0 + tx];
        __syncthreads();
        #pragma unroll
        for (int j = 0; j < 4; j++)
            g_WdtT[(size_t)(c0 + ty + 8 * j) * DTR + r0 + tx] = t[tx][ty + 8 * j];
        return;
    }
    bx -= 128;
    {                                 // W_out [2048][1024] -> [1024][2048] bf16
        int c0 = (bx & 31) * 32, r0 = (bx >> 5) * 32;
        #pragma unroll
        for (int j = 0; j < 4; j++)
            t[ty + 8 * j][tx] = Wout[(size_t)(r0 + ty + 8 * j) * DM + c0 + tx];
        __syncthreads();
        #pragma unroll
        for (int j = 0; j < 4; j++)
            g_WoutTh[(size_t)(c0 + ty + 8 * j) * DI + r0 + tx] =
                __float2bfloat16_rn(t[tx][ty + 8 * j]);
    }
}

// LayerNorm + (1+scale)*xn + shift -> g_hh (bf16)
__global__ void k_ln(const float* __restrict__ x) {
    int row = blockIdx.x;
    int b = row >> 11;
    const float4* xr = (const float4*)(x + (size_t)row * DM);
    float4 v = xr[threadIdx.x];
    float s = v.x + v.y + v.z + v.w;
    float q = v.x * v.x + v.y * v.y + v.z * v.z + v.w * v.w;
    #pragma unroll
    for (int o = 16; o; o >>= 1) {
        s += __shfl_xor_sync(0xffffffffu, s, o);
        q += __shfl_xor_sync(0xffffffffu, q, o);
    }
    __shared__ float ss[8], sq[8];
    int w = threadIdx.x >> 5;
    if ((threadIdx.x & 31) == 0) { ss[w] = s; sq[w] = q; }
    __syncthreads();
    s = 0.f; q = 0.f;
    #pragma unroll
    for (int i = 0; i < 8; i++) { s += ss[i]; q += sq[i]; }
    float mean = s * (1.f / DM);
    float var  = q * (1.f / DM) - mean * mean;
    float rstd = rsqrtf(var + 1e-6f);
    int col = threadIdx.x * 4;
    float4 sc4 = *(const float4*)(g_mod + b * 3 * DM + col);
    float4 sh4 = *(const float4*)(g_mod + b * 3 * DM + DM + col);
    float o0 = (v.x - mean) * rstd * (1.f + sc4.x) + sh4.x;
    float o1 = (v.y - mean) * rstd * (1.f + sc4.y) + sh4.y;
    float o2 = (v.z - mean) * rstd * (1.f + sc4.z) + sh4.z;
    float o3 = (v.w - mean) * rstd * (1.f + sc4.w) + sh4.w;
    __nv_bfloat162 h0 = __floats2bfloat162_rn(o0, o1);
    __nv_bfloat162 h1 = __floats2bfloat162_rn(o2, o3);
    uint2 u;
    u.x = *(uint32_t*)&h0;
    u.y = *(uint32_t*)&h1;
    *(uint2*)(g_hh + (size_t)row * DM + col) = u;
}

// depthwise causal conv (kernel 4) + silu on bf16 xz -> bf16 xc. 2 channels/thread.
__global__ void k_conv(const float* __restrict__ cw, const float* __restrict__ cb) {
    int i = blockIdx.x * blockDim.x + threadIdx.x;    // 0 .. ROWS*DI/2-1
    int d2 = i & 1023;
    int row = i >> 10;
    int l = row & (L - 1);
    int d = d2 << 1;
    const __nv_bfloat162* xm = (const __nv_bfloat162*)g_xzh;   // row stride = 2048 pairs
    size_t rb = (size_t)row * 2048 + d2;
    float4 wa = *(const float4*)(cw + 4 * d);
    float4 wb = *(const float4*)(cw + 4 * d + 4);
    float2 c2 = *(const float2*)(cb + d);
    float2 x0 = __bfloat1622float2(xm[rb]);
    float ax = fmaf(x0.x, wa.w, c2.x);
    float ay = fmaf(x0.y, wb.w, c2.y);
    if (l >= 1) { float2 x1 = __bfloat1622float2(xm[rb - 2048]);
                  ax = fmaf(x1.x, wa.z, ax); ay = fmaf(x1.y, wb.z, ay); }
    if (l >= 2) { float2 x1 = __bfloat1622float2(xm[rb - 2 * 2048]);
                  ax = fmaf(x1.x, wa.y, ax); ay = fmaf(x1.y, wb.y, ay); }
    if (l >= 3) { float2 x1 = __bfloat1622float2(xm[rb - 3 * 2048]);
                  ax = fmaf(x1.x, wa.x, ax); ay = fmaf(x1.y, wb.x, ay); }
    float sx = ax / (1.f + __expf(-ax));
    float sy = ay / (1.f + __expf(-ay));
    ((__nv_bfloat162*)g_xch)[(size_t)row * 1024 + d2] = __floats2bfloat162_rn(sx, sy);
}

// ---------------- selective scan, smem-staged + cp.async double buffer ----------
// 128 blocks = 4 b x 32 tiles of 64 channels; 256 thr = 64 ch x 4 state-quads.
// Chunks of T=32 timesteps staged in smem; recurrence reads smem only.
__global__ __launch_bounds__(256)
void k_scan(const float* __restrict__ Alog, const float* __restrict__ Dskip,
            __nv_bfloat16* __restrict__ outp) {
    __shared__ float         sD[2][32][64];     // delta
    __shared__ __nv_bfloat16 sU[2][32][64];     // conv+silu u
    __shared__ __nv_bfloat16 sZ[2][32][64];     // z gate input
    __shared__ float         sBC[2][32][32];    // B(16) | C(16)
    __shared__ __nv_bfloat16 sY[32][64];        // output staging

    const int tid = threadIdx.x;
    const int q = tid & 3, ch = tid >> 2;       // ch 0..63
    const int bx = blockIdx.x;
    const int b = bx >> 5;
    const int d0 = (bx & 31) * 64;
    const int d = d0 + ch;
    const size_t rb = (size_t)b * L;

    float Ar[4];
    #pragma unroll
    for (int s = 0; s < 4; s++) Ar[s] = -__expf(Alog[d * DS + q * 4 + s]);
    const float Dsk = Dskip[d];
    float h[4] = {0.f, 0.f, 0.f, 0.f};

    auto issue = [&](int buf, int l0) {
        #pragma unroll
        for (int i = 0; i < 2; i++) {           // delta: 32 rows x 256B
            int idx = tid + i * 256;
            int r = idx >> 4, cc = idx & 15;
            cp_async16(smem_u32(&sD[buf][r][cc * 4]),
                       g_delta + (rb + l0 + r) * DI + d0 + cc * 4);
        }
        {
            int r = tid >> 3, cc = tid & 7;     // 32 rows x 128B each
            cp_async16(smem_u32(&sU[buf][r][cc * 8]),
                       g_xch + (rb + l0 + r) * DI + d0 + cc * 8);
            cp_async16(smem_u32(&sZ[buf][r][cc * 8]),
                       g_xzh + (rb + l0 + r) * (2 * DI) + DI + d0 + cc * 8);
            cp_async16(smem_u32(&sBC[buf][r][cc * 4]),
                       g_dbc + (rb + l0 + r) * DBCP + DTR + cc * 4);
        }
        CP_COMMIT();
    };

    issue(0, 0);
    issue(1, 32);

    for (int c = 0; c < 64; c++) {
        CP_WAIT1();
        __syncthreads();
        const int buf = c & 1;
        #pragma unroll 4
        for (int t = 0; t < 32; t++) {
            float delta = sD[buf][t][ch];
            float u = __bfloat162float(sU[buf][t][ch]);
            float4 Bv = *(const float4*)&sBC[buf][t][q * 4];
            float4 Cv = *(const float4*)&sBC[buf][t][16 + q * 4];
            float du = delta * u;
            float dA0 = __expf(delta * Ar[0]);
            float dA1 = __expf(delta * Ar[1]);
            float dA2 = __expf(delta * Ar[2]);
            float dA3 = __expf(delta * Ar[3]);
            float y;
            h[0] = fmaf(dA0, h[0], du * Bv.x); y = h[0] * Cv.x;
            h[1] = fmaf(dA1, h[1], du * Bv.y); y = fmaf(h[1], Cv.y, y);
            h[2] = fmaf(dA2, h[2], du * Bv.z); y = fmaf(h[2], Cv.z, y);
            h[3] = fmaf(dA3, h[3], du * Bv.w); y = fmaf(h[3], Cv.w, y);
            y += __shfl_xor_sync(0xffffffffu, y, 1);
            y += __shfl_xor_sync(0xffffffffu, y, 2);
            if (q == 0) {
                float z = __bfloat162float(sZ[buf][t][ch]);
                float yy = y + u * Dsk;
                float sig = 1.f / (1.f + __expf(-z));
                sY[t][ch] = __float2bfloat16_rn(yy * (z * sig));
            }
        }
        __syncthreads();
        {
            int r = tid >> 3, cc = tid & 7;     // bulk store 32 x 128B
            *(uint4*)(outp + (rb + c * 32 + r) * DI + d0 + cc * 8) =
                *(const uint4*)&sY[r][cc * 8];
        }
        if (c + 2 < 64) issue(buf, (c + 2) * 32);
        CP_COMMIT();
    }
}

// ---------------- bf16 mma.sync GEMM, cp.async 3-stage pipeline + ldmatrix ----------
// EPI 0: fp32 out plain   EPI 2: fp32 out res+gate*acc   EPI 3: bf16 out plain
template <int EPI>
__global__ __launch_bounds__(256, 2)
void gemm_bf16(int K, int lda, int ldb, int ldc,
               const __nv_bfloat16* __restrict__ A, const __nv_bfloat16* __restrict__ Bt,
               void* __restrict__ Cv,
               const float* __restrict__ res) {
    extern __shared__ char smc[];             // 3 stages x 20480 B (A|B)
    const int tid = threadIdx.x;
    const int wid = tid >> 5, lane = tid & 31;
    const int g = lane >> 2, t4 = lane & 3;
    const int wm = wid & 1, wn = wid >> 1;
    const int rowBase = blockIdx.y * 128, colBase = blockIdx.x * 128;
    const __nv_bfloat16* Ab = A  + (size_t)rowBase * lda;
    const __nv_bfloat16* Bp = Bt + (size_t)colBase * ldb;
    const uint32_t smemB = smem_u32(smc);

    const uint32_t aOff = (uint32_t)((wm * 64 + (lane & 15)) * 80 + ((lane >> 4) << 4));
    const uint32_t bOff = (uint32_t)((wn * 32 + ((lane >> 4) << 3) + (lane & 7)) * 80
                                     + (((lane >> 3) & 1) << 4));

    float acc[4][4][4];
    #pragma unroll
    for (int m = 0; m < 4; m++)
        #pragma unroll
        for (int n = 0; n < 4; n++)
            #pragma unroll
            for (int e = 0; e < 4; e++) acc[m][n][e] = 0.f;

    auto issue_stage = [&](int s, int k0) {
        uint32_t sb = smemB + (uint32_t)s * 20480u;
        #pragma unroll
        for (int i = 0; i < 2; i++) {
            int idx = tid + i * 256;
            int r = idx >> 2, ch = idx & 3;
            uint32_t doff = (uint32_t)(r * 80 + ch * 16);
            cp_async16(sb + doff, Ab + (size_t)r * lda + k0 + ch * 8);
            cp_async16(sb + 10240u + doff, Bp + (size_t)r * ldb + k0 + ch * 8);
        }
        CP_COMMIT();
    };

    const int nk = K >> 5;
    issue_stage(0, 0);
    issue_stage(1, 32);

    for (int k = 0; k < nk; k++) {
        CP_WAIT1();
        __syncthreads();
        if (k + 2 < nk) issue_stage((k + 2) % 3, (k + 2) * 32);
        else CP_COMMIT();

        const uint32_t sA = smemB + (uint32_t)((k % 3) * 20480);
        const uint32_t sB = sA + 10240u;
        #pragma unroll
        for (int s = 0; s < 2; s++) {
            uint32_t af[4][4], bf[4][2];
            #pragma unroll
            for (int m = 0; m < 4; m++)
                ldsm_x4(af[m], sA + aOff + (uint32_t)(m * 16 * 80 + s * 32));
            #pragma unroll
            for (int p = 0; p < 2; p++) {
                uint32_t rbv[4];
                ldsm_x4(rbv, sB + bOff + (uint32_t)(p * 16 * 80 + s * 32));
                bf[2 * p + 0][0] = rbv[0];
                bf[2 * p + 0][1] = rbv[1];
                bf[2 * p + 1][0] = rbv[2];
                bf[2 * p + 1][1] = rbv[3];
            }
            #pragma unroll
            for (int m = 0; m < 4; m++)
                #pragma unroll
                for (int n = 0; n < 4; n++)
                    mma_bf16(acc[m][n], af[m], bf[n]);
        }
        __syncthreads();
    }

    #pragma unroll
    for (int m = 0; m < 4; m++) {
        int r0 = rowBase + wm * 64 + m * 16 + g;
        #pragma unroll
        for (int n = 0; n < 4; n++) {
            int col = colBase + wn * 32 + n * 8 + 2 * t4;
            #pragma unroll
            for (int h = 0; h < 2; h++) {
                int r = r0 + h * 8;
                float e0 = acc[m][n][2 * h + 0];
                float e1 = acc[m][n][2 * h + 1];
                if (EPI == 2) {
                    float2 gp = *(const float2*)(g_mod + (r >> 11) * 3 * DM + 2 * DM + col);
                    float2 rp = *(const float2*)(res + (size_t)r * ldc + col);
                    e0 = rp.x + gp.x * e0;
                    e1 = rp.y + gp.y * e1;
                }
                if (EPI == 3) {
                    __nv_bfloat162 pk = __floats2bfloat162_rn(e0, e1);
                    *(__nv_bfloat162*)((__nv_bfloat16*)Cv + (size_t)r * ldc + col) = pk;
                } else {
                    float2 v2;
                    v2.x = e0;
                    v2.y = e1;
                    *(float2*)((float*)Cv + (size_t)r * ldc + col) = v2;
                }
            }
        }
    }
}

// ---------------- tf32 mma.sync GEMM (fp32 in) for delta GEMM ----------------
// EPI 1: softplus(acc + bias[n])  (branchless cheap softplus)
template <int EPI>
__global__ __launch_bounds__(256, 2)
void gemm_mma(int K, int lda, int ldb, int ldc,
              const float* __restrict__ A, const float* __restrict__ Bt,
              float* __restrict__ C,
              const float* __restrict__ bias) {
    extern __shared__ float smem[];
    const int tid = threadIdx.x;
    const int wid = tid >> 5, lane = tid & 31;
    const int g = lane >> 2, t4 = lane & 3;
    const int wm = wid & 1, wn = wid >> 1;
    const int rowBase = blockIdx.y * 128, colBase = blockIdx.x * 128;
    const float* Ab = A  + (size_t)rowBase * lda;
    const float* Bp = Bt + (size_t)colBase * ldb;
    const uint32_t smemB = smem_u32(smem);

    float acc[4][4][4];
    #pragma unroll
    for (int m = 0; m < 4; m++)
        #pragma unroll
        for (int n = 0; n < 4; n++)
            #pragma unroll
            for (int e = 0; e < 4; e++) acc[m][n][e] = 0.f;

    auto issue_stage = [&](int s, int k0) {
        uint32_t sb = smemB + (uint32_t)s * 8192u * 4u;
        #pragma unroll
        for (int i = 0; i < 4; i++) {
            int idx = tid + i * 256;
            int r = idx >> 3, cch = idx & 7;
            uint32_t doff = ((uint32_t)(r * 32 + ((cch ^ (r & 7)) << 2))) * 4u;
            cp_async16(sb + doff, Ab + (size_t)r * lda + k0 + cch * 4);
            cp_async16(sb + 16384u + doff, Bp + (size_t)r * ldb + k0 + cch * 4);
        }
        CP_COMMIT();
    };

    const int nk = K >> 5;
    issue_stage(0, 0);
    issue_stage(1, 32);

    for (int k = 0; k < nk; k++) {
        CP_WAIT1();
        __syncthreads();
        if (k + 2 < nk) issue_stage((k + 2) % 3, (k + 2) * 32);
        else CP_COMMIT();

        const float* sA = smem + (k % 3) * 8192;
        const float* sB = sA + 4096;
        const int aR = wm * 64 + g;
        const int bR = wn * 32 + g;
        #pragma unroll
        for (int kk = 0; kk < 4; kk++) {
            const int c0 = (((kk * 2 + 0) ^ g) << 2) + t4;
            const int c1 = (((kk * 2 + 1) ^ g) << 2) + t4;
            uint32_t af[4][4], bf[4][2];
            #pragma unroll
            for (int m = 0; m < 4; m++) {
                const float* p = sA + (aR + m * 16) * 32;
                af[m][0] = __float_as_uint(p[c0]);
                af[m][1] = __float_as_uint(p[8 * 32 + c0]);
                af[m][2] = __float_as_uint(p[c1]);
                af[m][3] = __float_as_uint(p[8 * 32 + c1]);
            }
            #pragma unroll
            for (int n = 0; n < 4; n++) {
                const float* p = sB + (bR + n * 8) * 32;
                bf[n][0] = __float_as_uint(p[c0]);
                bf[n][1] = __float_as_uint(p[c1]);
            }
            #pragma unroll
            for (int m = 0; m < 4; m++)
                #pragma unroll
                for (int n = 0; n < 4; n++)
                    mma_tf32(acc[m][n], af[m], bf[n]);
        }
        __syncthreads();
    }

    #pragma unroll
    for (int m = 0; m < 4; m++) {
        int r0 = rowBase + wm * 64 + m * 16 + g;
        #pragma unroll
        for (int n = 0; n < 4; n++) {
            int col = colBase + wn * 32 + n * 8 + 2 * t4;
            #pragma unroll
            for (int h = 0; h < 2; h++) {
                int r = r0 + h * 8;
                float e0 = acc[m][n][2 * h + 0];
                float e1 = acc[m][n][2 * h + 1];
                if (EPI == 1) {
                    float2 bb = *(const float2*)(bias + col);
                    e0 += bb.x;
                    e1 += bb.y;
                    e0 = fmaxf(e0, 0.f) + __logf(1.f + __expf(-fabsf(e0)));
                    e1 = fmaxf(e1, 0.f) + __logf(1.f + __expf(-fabsf(e1)));
                }
                float2 v2;
                v2.x = e0;
                v2.y = e1;
                *(float2*)(C + (size_t)r * ldc + col) = v2;
            }
        }
    }
}

// ---------------- launch ----------------
extern "C" void kernel_launch(void* const* d_in, const int* in_sizes, int n_in,
                              void* d_out, int out_size) {
    const float* x      = (const float*)d_in[0];
    const float* c      = (const float*)d_in[1];
    const float* W_in   = (const float*)d_in[2];
    const float* conv_w = (const float*)d_in[3];
    const float* conv_b = (const float*)d_in[4];
    const float* W_xp   = (const float*)d_in[5];
    const float* W_dt   = (const float*)d_in[6];
    const float* b_dt   = (const float*)d_in[7];
    const float* A_log  = (const float*)d_in[8];
    const float* D_skip = (const float*)d_in[9];
    const float* W_out  = (const float*)d_in[10];
    const float* W_ada  = (const float*)d_in[11];
    const float* b_ada  = (const float*)d_in[12];
    float* out = (float*)d_out;

    float *p_dbc, *p_delta, *p_WdtT;
    __nv_bfloat16 *p_hh, *p_xzh, *p_xch, *p_ymulh, *p_WinTh, *p_WxpTh, *p_WoutTh;
    cudaGetSymbolAddress((void**)&p_hh,     g_hh);
    cudaGetSymbolAddress((void**)&p_xzh,    g_xzh);
    cudaGetSymbolAddress((void**)&p_xch,    g_xch);
    cudaGetSymbolAddress((void**)&p_dbc,    g_dbc);
    cudaGetSymbolAddress((void**)&p_delta,  g_delta);
    cudaGetSymbolAddress((void**)&p_ymulh,  g_ymulh);
    cudaGetSymbolAddress((void**)&p_WinTh,  g_WinTh);
    cudaGetSymbolAddress((void**)&p_WxpTh,  g_WxpTh);
    cudaGetSymbolAddress((void**)&p_WdtT,   g_WdtT);
    cudaGetSymbolAddress((void**)&p_WoutTh, g_WoutTh);

    constexpr int SMEM_TF32 = 3 * 8192 * sizeof(float);   // 96 KB
    constexpr int SMEM_BF16 = 3 * 20480;                  // 60 KB
    cudaFuncSetAttribute(gemm_bf16<0>, cudaFuncAttributeMaxDynamicSharedMemorySize, SMEM_BF16);
    cudaFuncSetAttribute(gemm_bf16<2>, cudaFuncAttributeMaxDynamicSharedMemorySize, SMEM_BF16);
    cudaFuncSetAttribute(gemm_bf16<3>, cudaFuncAttributeMaxDynamicSharedMemorySize, SMEM_BF16);
    cudaFuncSetAttribute(gemm_mma<1>,  cudaFuncAttributeMaxDynamicSharedMemorySize, SMEM_TF32);

    // 0) fused ada + all weight transposes
    k_pre<<<6576, dim3(32, 8)>>>(c, W_ada, b_ada, W_in, W_xp, W_dt, W_out);
    // 1) LayerNorm + scale/shift -> bf16
    k_ln<<<ROWS, 256>>>(x);
    // 2) GEMM1 (bf16): h @ W_in -> xz (bf16)   [8192 x 4096, K=1024]
    gemm_bf16<3><<<dim3(2 * DI / 128, ROWS / 128), 256, SMEM_BF16>>>(
        DM, DM, DM, 2 * DI, p_hh, p_WinTh, p_xzh, nullptr);
    // 3) DUMMY scan for profiling (index 3 = ncu capture slot). Reads stale-but-
    //    deterministic buffers; writes g_ymulh which the real scan (step 7)
    //    fully overwrites before anything reads it.
    k_scan<<<128, 256>>>(A_log, D_skip, p_ymulh);
    // 4) conv + silu (bf16 -> bf16)
    k_conv<<<(ROWS * DI / 2) / 256, 256>>>(conv_w, conv_b);
    // 5) GEMM2 (bf16): xc @ W_xproj(pad 128) -> dbc fp32 [8192 x 128, K=2048]
    gemm_bf16<0><<<dim3(1, ROWS / 128), 256, SMEM_BF16>>>(
        DI, DI, DI, DBCP, p_xch, p_WxpTh, p_dbc, nullptr);
    // 6) delta GEMM (tf32): dbc[:, :64] @ W_dt + b_dt, softplus -> delta fp32
    gemm_mma<1><<<dim3(DI / 128, ROWS / 128), 256, SMEM_TF32>>>(
        DTR, DBCP, DTR, DI, p_dbc, p_WdtT, p_delta, b_dt);
    // 7) selective scan (smem-staged) + skip + silu(z) gate -> ymul (bf16)
    k_scan<<<128, 256>>>(A_log, D_skip, p_ymulh);
    // 8) GEMM3 (bf16): ymul @ W_out, fused residual + gate -> out
    gemm_bf16<2><<<dim3(DM / 128, ROWS / 128), 256, SMEM_BF16>>>(
        DI, DI, DI, DM, p_ymulh, p_WoutTh, out, x);
}

// round 17
// speedup vs baseline: 3.6040x; 1.8642x over previous
#include <cuda_runtime.h>
#include <cuda_bf16.h>
#include <cstdint>
#include <cstddef>

// ---------------- problem constants ----------------
static constexpr int Bb  = 4;
static constexpr int L   = 2048;
static constexpr int DM  = 1024;          // d_model
static constexpr int DI  = 2048;          // d_inner
static constexpr int DS  = 16;            // d_state
static constexpr int DTR = 64;            // dt_rank
static constexpr int ROWS = Bb * L;       // 8192
static constexpr int DBCP = 128;          // padded dt|B|C row (96 -> 128)
static constexpr int SEG  = 8;            // L segments for 2-pass scan
static constexpr int LSEG = L / SEG;      // 256
static constexpr int NCH  = Bb * DI;      // 8192 channels

// ---------------- scratch (device globals, no allocations) ----------------
__device__ float g_mod[Bb * 3 * DM];                      // scale|shift|gate
__device__ __nv_bfloat16 g_hh[(size_t)ROWS * DM];         // LN-modulated input
__device__ __nv_bfloat16 g_xzh[(size_t)ROWS * 2 * DI];    // x@W_in (xm | z) bf16
__device__ __nv_bfloat16 g_xch[(size_t)ROWS * DI];        // conv+silu bf16
__device__ float g_dbc[(size_t)ROWS * DBCP];              // dt | B | C | pad
__device__ float g_delta[(size_t)ROWS * DI];              // softplus(dt@W_dt+b)
__device__ __nv_bfloat16 g_ymulh[(size_t)ROWS * DI];      // (scan+u*D)*silu(z)
__device__ __nv_bfloat16 g_WinTh[(size_t)(2 * DI) * DM];  // W_in^T  bf16 [4096][1024]
__device__ __nv_bfloat16 g_WxpTh[(size_t)DBCP * DI];      // W_xp^T  bf16 [128][2048]
__device__ float g_WdtT[(size_t)DI * DTR];                // W_dt^T  fp32 [2048][64]
__device__ __nv_bfloat16 g_WoutTh[(size_t)DM * DI];       // W_out^T bf16 [1024][2048]
__device__ float g_vseg[(size_t)(SEG - 1) * NCH * DS];    // per-seg local final h
__device__ float g_Pseg[(size_t)(SEG - 1) * NCH * DS];    // per-seg prod(dA)
__device__ float g_hin [(size_t)SEG * NCH * DS];          // per-seg initial h

// ---------------- helpers ----------------
__device__ __forceinline__ uint32_t smem_u32(const void* p) {
    uint32_t a;
    asm("{ .reg .u64 t; cvta.to.shared.u64 t, %1; cvt.u32.u64 %0, t; }" : "=r"(a) : "l"(p));
    return a;
}
__device__ __forceinline__ void cp_async16(uint32_t dst, const void* src) {
    asm volatile("cp.async.cg.shared.global [%0], [%1], 16;"
                 :: "r"(dst), "l"(__cvta_generic_to_global(src)));
}
#define CP_COMMIT() asm volatile("cp.async.commit_group;" ::: "memory")
#define CP_WAIT1()  asm volatile("cp.async.wait_group 1;" ::: "memory")

__device__ __forceinline__ void mma_tf32(float* c, const uint32_t* a, const uint32_t* b) {
    asm volatile(
        "mma.sync.aligned.m16n8k8.row.col.f32.tf32.tf32.f32 "
        "{%0,%1,%2,%3}, {%4,%5,%6,%7}, {%8,%9}, {%0,%1,%2,%3};"
        : "+f"(c[0]), "+f"(c[1]), "+f"(c[2]), "+f"(c[3])
        : "r"(a[0]), "r"(a[1]), "r"(a[2]), "r"(a[3]), "r"(b[0]), "r"(b[1]));
}
__device__ __forceinline__ void mma_bf16(float* c, const uint32_t* a, const uint32_t* b) {
    asm volatile(
        "mma.sync.aligned.m16n8k16.row.col.f32.bf16.bf16.f32 "
        "{%0,%1,%2,%3}, {%4,%5,%6,%7}, {%8,%9}, {%0,%1,%2,%3};"
        : "+f"(c[0]), "+f"(c[1]), "+f"(c[2]), "+f"(c[3])
        : "r"(a[0]), "r"(a[1]), "r"(a[2]), "r"(a[3]), "r"(b[0]), "r"(b[1]));
}
__device__ __forceinline__ void ldsm_x4(uint32_t* r, uint32_t addr) {
    asm volatile("ldmatrix.sync.aligned.m8n8.x4.shared.b16 {%0,%1,%2,%3}, [%4];"
                 : "=r"(r[0]), "=r"(r[1]), "=r"(r[2]), "=r"(r[3]) : "r"(addr));
}

// ---------------- k_pre: fused ada + all weight transposes ----------------
__global__ void k_pre(const float* __restrict__ c,  const float* __restrict__ Wada,
                      const float* __restrict__ bada,
                      const float* __restrict__ Win, const float* __restrict__ Wxp,
                      const float* __restrict__ Wdt, const float* __restrict__ Wout) {
    int bx = blockIdx.x;
    int tx = threadIdx.x, ty = threadIdx.y;
    __shared__ float t[32][33];
    if (bx < 48) {
        __shared__ float sc[DM];
        int tid = ty * 32 + tx;
        int b = bx / 12;
        int j = (bx % 12) * 256 + tid;
        for (int k = tid; k < DM; k += 256) {
            float v = c[b * DM + k];
            sc[k] = v / (1.f + __expf(-v));
        }
        __syncthreads();
        float a[8];
        #pragma unroll
        for (int i = 0; i < 8; i++) a[i] = 0.f;
        for (int k = 0; k < DM; k += 8) {
            #pragma unroll
            for (int i = 0; i < 8; i++)
                a[i] += sc[k + i] * Wada[(size_t)(k + i) * (3 * DM) + j];
        }
        float s = 0.f;
        #pragma unroll
        for (int i = 0; i < 8; i++) s += a[i];
        g_mod[b * 3 * DM + j] = bada[j] + s;
        return;
    }
    bx -= 48;
    if (bx < 4096) {                  // W_in [1024][4096] -> [4096][1024] bf16
        int c0 = (bx & 127) * 32, r0 = (bx >> 7) * 32;
        #pragma unroll
        for (int j = 0; j < 4; j++)
            t[ty + 8 * j][tx] = Win[(size_t)(r0 + ty + 8 * j) * (2 * DI) + c0 + tx];
        __syncthreads();
        #pragma unroll
        for (int j = 0; j < 4; j++)
            g_WinTh[(size_t)(c0 + ty + 8 * j) * DM + r0 + tx] =
                __float2bfloat16_rn(t[tx][ty + 8 * j]);
        return;
    }
    bx -= 4096;
    if (bx < 256) {                   // W_xp [2048][96] -> [128][2048] bf16, rows 96..127 = 0
        int dty = bx & 3, dtx = bx >> 2;
        int dr0 = dty * 32, dc0 = dtx * 32;
        if (dty == 3) {
            #pragma unroll
            for (int j = 0; j < 4; j++)
                g_WxpTh[(size_t)(dr0 + ty + 8 * j) * DI + dc0 + tx] = __float2bfloat16_rn(0.f);
            return;
        }
        #pragma unroll
        for (int j = 0; j < 4; j++)
            t[ty + 8 * j][tx] = Wxp[(size_t)(dc0 + ty + 8 * j) * 96 + dr0 + tx];
        __syncthreads();
        #pragma unroll
        for (int j = 0; j < 4; j++)
            g_WxpTh[(size_t)(dr0 + ty + 8 * j) * DI + dc0 + tx] =
                __float2bfloat16_rn(t[tx][ty + 8 * j]);
        return;
    }
    bx -= 256;
    if (bx < 128) {                   // W_dt [64][2048] -> [2048][64] fp32
        int c0 = (bx & 63) * 32, r0 = (bx >> 6) * 32;
        #pragma unroll
        for (int j = 0; j < 4; j++)
            t[ty + 8 * j][tx] = Wdt[(size_t)(r0 + ty + 8 * j) * DI + c0 + tx];
        __syncthreads();
        #pragma unroll
        for (int j = 0; j < 4; j++)
            g_WdtT[(size_t)(c0 + ty + 8 * j) * DTR + r0 + tx] = t[tx][ty + 8 * j];
        return;
    }
    bx -= 128;
    {                                 // W_out [2048][1024] -> [1024][2048] bf16
        int c0 = (bx & 31) * 32, r0 = (bx >> 5) * 32;
        #pragma unroll
        for (int j = 0; j < 4; j++)
            t[ty + 8 * j][tx] = Wout[(size_t)(r0 + ty + 8 * j) * DM + c0 + tx];
        __syncthreads();
        #pragma unroll
        for (int j = 0; j < 4; j++)
            g_WoutTh[(size_t)(c0 + ty + 8 * j) * DI + r0 + tx] =
                __float2bfloat16_rn(t[tx][ty + 8 * j]);
    }
}

// LayerNorm + (1+scale)*xn + shift -> g_hh (bf16)
__global__ void k_ln(const float* __restrict__ x) {
    int row = blockIdx.x;
    int b = row >> 11;
    const float4* xr = (const float4*)(x + (size_t)row * DM);
    float4 v = xr[threadIdx.x];
    float s = v.x + v.y + v.z + v.w;
    float q = v.x * v.x + v.y * v.y + v.z * v.z + v.w * v.w;
    #pragma unroll
    for (int o = 16; o; o >>= 1) {
        s += __shfl_xor_sync(0xffffffffu, s, o);
        q += __shfl_xor_sync(0xffffffffu, q, o);
    }
    __shared__ float ss[8], sq[8];
    int w = threadIdx.x >> 5;
    if ((threadIdx.x & 31) == 0) { ss[w] = s; sq[w] = q; }
    __syncthreads();
    s = 0.f; q = 0.f;
    #pragma unroll
    for (int i = 0; i < 8; i++) { s += ss[i]; q += sq[i]; }
    float mean = s * (1.f / DM);
    float var  = q * (1.f / DM) - mean * mean;
    float rstd = rsqrtf(var + 1e-6f);
    int col = threadIdx.x * 4;
    float4 sc4 = *(const float4*)(g_mod + b * 3 * DM + col);
    float4 sh4 = *(const float4*)(g_mod + b * 3 * DM + DM + col);
    float o0 = (v.x - mean) * rstd * (1.f + sc4.x) + sh4.x;
    float o1 = (v.y - mean) * rstd * (1.f + sc4.y) + sh4.y;
    float o2 = (v.z - mean) * rstd * (1.f + sc4.z) + sh4.z;
    float o3 = (v.w - mean) * rstd * (1.f + sc4.w) + sh4.w;
    __nv_bfloat162 h0 = __floats2bfloat162_rn(o0, o1);
    __nv_bfloat162 h1 = __floats2bfloat162_rn(o2, o3);
    uint2 u;
    u.x = *(uint32_t*)&h0;
    u.y = *(uint32_t*)&h1;
    *(uint2*)(g_hh + (size_t)row * DM + col) = u;
}

// depthwise causal conv (kernel 4) + silu on bf16 xz -> bf16 xc. 2 channels/thread.
__global__ void k_conv(const float* __restrict__ cw, const float* __restrict__ cb) {
    int i = blockIdx.x * blockDim.x + threadIdx.x;    // 0 .. ROWS*DI/2-1
    int d2 = i & 1023;
    int row = i >> 10;
    int l = row & (L - 1);
    int d = d2 << 1;
    const __nv_bfloat162* xm = (const __nv_bfloat162*)g_xzh;   // row stride = 2048 pairs
    size_t rb = (size_t)row * 2048 + d2;
    float4 wa = *(const float4*)(cw + 4 * d);
    float4 wb = *(const float4*)(cw + 4 * d + 4);
    float2 c2 = *(const float2*)(cb + d);
    float2 x0 = __bfloat1622float2(xm[rb]);
    float ax = fmaf(x0.x, wa.w, c2.x);
    float ay = fmaf(x0.y, wb.w, c2.y);
    if (l >= 1) { float2 x1 = __bfloat1622float2(xm[rb - 2048]);
                  ax = fmaf(x1.x, wa.z, ax); ay = fmaf(x1.y, wb.z, ay); }
    if (l >= 2) { float2 x1 = __bfloat1622float2(xm[rb - 2 * 2048]);
                  ax = fmaf(x1.x, wa.y, ax); ay = fmaf(x1.y, wb.y, ay); }
    if (l >= 3) { float2 x1 = __bfloat1622float2(xm[rb - 3 * 2048]);
                  ax = fmaf(x1.x, wa.x, ax); ay = fmaf(x1.y, wb.x, ay); }
    float sx = ax / (1.f + __expf(-ax));
    float sy = ay / (1.f + __expf(-ay));
    ((__nv_bfloat162*)g_xch)[(size_t)row * 1024 + d2] = __floats2bfloat162_rn(sx, sy);
}

// ---------------- 2-pass selective scan --------------------------------------
// Pass 1: segments 0..SEG-2, recurrence only. Emits v (local final h) and
// P (prod dA) per (channel, state). grid (128, SEG-1), block 256 = 64ch x 4q.
__global__ __launch_bounds__(256)
void k_scan1(const float* __restrict__ Alog) {
    __shared__ float         sD[2][32][64];
    __shared__ __nv_bfloat16 sU[2][32][64];
    __shared__ float         sB[2][32][16];

    const int tid = threadIdx.x;
    const int q = tid & 3, ch = tid >> 2;
    const int bx = blockIdx.x;
    const int seg = blockIdx.y;
    const int b = bx >> 5;
    const int d0 = (bx & 31) * 64;
    const int d = d0 + ch;
    const size_t rb = (size_t)b * L + (size_t)seg * LSEG;

    float Ar[4];
    #pragma unroll
    for (int s = 0; s < 4; s++) Ar[s] = -__expf(Alog[d * DS + q * 4 + s]);
    float h[4] = {0.f, 0.f, 0.f, 0.f};
    float P[4] = {1.f, 1.f, 1.f, 1.f};

    auto issue = [&](int buf, int l0) {
        #pragma unroll
        for (int i = 0; i < 2; i++) {
            int idx = tid + i * 256;
            int r = idx >> 4, cc = idx & 15;
            cp_async16(smem_u32(&sD[buf][r][cc * 4]),
                       g_delta + (rb + l0 + r) * DI + d0 + cc * 4);
        }
        {
            int r = tid >> 3, cc = tid & 7;
            cp_async16(smem_u32(&sU[buf][r][cc * 8]),
                       g_xch + (rb + l0 + r) * DI + d0 + cc * 8);
        }
        if (tid < 128) {
            int r = tid >> 2, cc = tid & 3;
            cp_async16(smem_u32(&sB[buf][r][cc * 4]),
                       g_dbc + (rb + l0 + r) * DBCP + DTR + cc * 4);
        }
        CP_COMMIT();
    };

    issue(0, 0);
    issue(1, 32);

    const int nc = LSEG / 32;         // 8 chunks
    for (int c = 0; c < nc; c++) {
        CP_WAIT1();
        __syncthreads();
        const int buf = c & 1;
        #pragma unroll 4
        for (int t = 0; t < 32; t++) {
            float delta = sD[buf][t][ch];
            float u = __bfloat162float(sU[buf][t][ch]);
            float4 Bv = *(const float4*)&sB[buf][t][q * 4];
            float du = delta * u;
            float dA0 = __expf(delta * Ar[0]);
            float dA1 = __expf(delta * Ar[1]);
            float dA2 = __expf(delta * Ar[2]);
            float dA3 = __expf(delta * Ar[3]);
            P[0] *= dA0; h[0] = fmaf(dA0, h[0], du * Bv.x);
            P[1] *= dA1; h[1] = fmaf(dA1, h[1], du * Bv.y);
            P[2] *= dA2; h[2] = fmaf(dA2, h[2], du * Bv.z);
            P[3] *= dA3; h[3] = fmaf(dA3, h[3], du * Bv.w);
        }
        __syncthreads();
        if (c + 2 < nc) issue(buf, (c + 2) * 32);
        else CP_COMMIT();
    }

    size_t o = ((size_t)seg * NCH + (size_t)b * DI + d) * DS + q * 4;
    float4 v4, p4;
    v4.x = h[0]; v4.y = h[1]; v4.z = h[2]; v4.w = h[3];
    p4.x = P[0]; p4.y = P[1]; p4.z = P[2]; p4.w = P[3];
    *(float4*)&g_vseg[o] = v4;
    *(float4*)&g_Pseg[o] = p4;
}

// Combine: per (channel, state-quad) sequential prefix over SEG segments.
__global__ void k_comb() {
    int t = blockIdx.x * blockDim.x + threadIdx.x;   // 0 .. NCH*4-1
    int ch = t >> 2, q = t & 3;
    float4 h;
    h.x = 0.f; h.y = 0.f; h.z = 0.f; h.w = 0.f;
    #pragma unroll
    for (int seg = 0; seg < SEG; seg++) {
        size_t o = ((size_t)seg * NCH + ch) * DS + q * 4;
        *(float4*)&g_hin[o] = h;
        if (seg < SEG - 1) {
            float4 P = *(const float4*)&g_Pseg[o];
            float4 v = *(const float4*)&g_vseg[o];
            h.x = fmaf(P.x, h.x, v.x);
            h.y = fmaf(P.y, h.y, v.y);
            h.z = fmaf(P.z, h.z, v.z);
            h.w = fmaf(P.w, h.w, v.w);
        }
    }
}

// Pass 2: full scan per segment seeded with h_in. grid (128, SEG), block 256.
__global__ __launch_bounds__(256)
void k_scan2(const float* __restrict__ Alog, const float* __restrict__ Dskip,
             __nv_bfloat16* __restrict__ outp) {
    __shared__ float         sD[2][32][64];
    __shared__ __nv_bfloat16 sU[2][32][64];
    __shared__ __nv_bfloat16 sZ[2][32][64];
    __shared__ float         sBC[2][32][32];
    __shared__ __nv_bfloat16 sY[32][64];

    const int tid = threadIdx.x;
    const int q = tid & 3, ch = tid >> 2;
    const int bx = blockIdx.x;
    const int seg = blockIdx.y;
    const int b = bx >> 5;
    const int d0 = (bx & 31) * 64;
    const int d = d0 + ch;
    const size_t rb = (size_t)b * L + (size_t)seg * LSEG;

    float Ar[4];
    #pragma unroll
    for (int s = 0; s < 4; s++) Ar[s] = -__expf(Alog[d * DS + q * 4 + s]);
    const float Dsk = Dskip[d];
    float4 h4 = *(const float4*)&g_hin[((size_t)seg * NCH + (size_t)b * DI + d) * DS + q * 4];
    float h[4] = {h4.x, h4.y, h4.z, h4.w};

    auto issue = [&](int buf, int l0) {
        #pragma unroll
        for (int i = 0; i < 2; i++) {
            int idx = tid + i * 256;
            int r = idx >> 4, cc = idx & 15;
            cp_async16(smem_u32(&sD[buf][r][cc * 4]),
                       g_delta + (rb + l0 + r) * DI + d0 + cc * 4);
        }
        {
            int r = tid >> 3, cc = tid & 7;
            cp_async16(smem_u32(&sU[buf][r][cc * 8]),
                       g_xch + (rb + l0 + r) * DI + d0 + cc * 8);
            cp_async16(smem_u32(&sZ[buf][r][cc * 8]),
                       g_xzh + (rb + l0 + r) * (2 * DI) + DI + d0 + cc * 8);
            cp_async16(smem_u32(&sBC[buf][r][cc * 4]),
                       g_dbc + (rb + l0 + r) * DBCP + DTR + cc * 4);
        }
        CP_COMMIT();
    };

    issue(0, 0);
    issue(1, 32);

    const int nc = LSEG / 32;         // 8 chunks
    for (int c = 0; c < nc; c++) {
        CP_WAIT1();
        __syncthreads();
        const int buf = c & 1;
        #pragma unroll 4
        for (int t = 0; t < 32; t++) {
            float delta = sD[buf][t][ch];
            float u = __bfloat162float(sU[buf][t][ch]);
            float4 Bv = *(const float4*)&sBC[buf][t][q * 4];
            float4 Cv = *(const float4*)&sBC[buf][t][16 + q * 4];
            float du = delta * u;
            float dA0 = __expf(delta * Ar[0]);
            float dA1 = __expf(delta * Ar[1]);
            float dA2 = __expf(delta * Ar[2]);
            float dA3 = __expf(delta * Ar[3]);
            float y;
            h[0] = fmaf(dA0, h[0], du * Bv.x); y = h[0] * Cv.x;
            h[1] = fmaf(dA1, h[1], du * Bv.y); y = fmaf(h[1], Cv.y, y);
            h[2] = fmaf(dA2, h[2], du * Bv.z); y = fmaf(h[2], Cv.z, y);
            h[3] = fmaf(dA3, h[3], du * Bv.w); y = fmaf(h[3], Cv.w, y);
            y += __shfl_xor_sync(0xffffffffu, y, 1);
            y += __shfl_xor_sync(0xffffffffu, y, 2);
            if (q == 0) {
                float z = __bfloat162float(sZ[buf][t][ch]);
                float yy = y + u * Dsk;
                float sig = 1.f / (1.f + __expf(-z));
                sY[t][ch] = __float2bfloat16_rn(yy * (z * sig));
            }
        }
        __syncthreads();
        {
            int r = tid >> 3, cc = tid & 7;
            *(uint4*)(outp + (rb + c * 32 + r) * DI + d0 + cc * 8) =
                *(const uint4*)&sY[r][cc * 8];
        }
        if (c + 2 < nc) issue(buf, (c + 2) * 32);
        else CP_COMMIT();
    }
}

// ---------------- bf16 mma.sync GEMM, cp.async 3-stage pipeline + ldmatrix ----------
// EPI 0: fp32 out plain   EPI 2: fp32 out res+gate*acc   EPI 3: bf16 out plain
template <int EPI>
__global__ __launch_bounds__(256, 2)
void gemm_bf16(int K, int lda, int ldb, int ldc,
               const __nv_bfloat16* __restrict__ A, const __nv_bfloat16* __restrict__ Bt,
               void* __restrict__ Cv,
               const float* __restrict__ res) {
    extern __shared__ char smc[];             // 3 stages x 20480 B (A|B)
    const int tid = threadIdx.x;
    const int wid = tid >> 5, lane = tid & 31;
    const int g = lane >> 2, t4 = lane & 3;
    const int wm = wid & 1, wn = wid >> 1;
    const int rowBase = blockIdx.y * 128, colBase = blockIdx.x * 128;
    const __nv_bfloat16* Ab = A  + (size_t)rowBase * lda;
    const __nv_bfloat16* Bp = Bt + (size_t)colBase * ldb;
    const uint32_t smemB = smem_u32(smc);

    const uint32_t aOff = (uint32_t)((wm * 64 + (lane & 15)) * 80 + ((lane >> 4) << 4));
    const uint32_t bOff = (uint32_t)((wn * 32 + ((lane >> 4) << 3) + (lane & 7)) * 80
                                     + (((lane >> 3) & 1) << 4));

    float acc[4][4][4];
    #pragma unroll
    for (int m = 0; m < 4; m++)
        #pragma unroll
        for (int n = 0; n < 4; n++)
            #pragma unroll
            for (int e = 0; e < 4; e++) acc[m][n][e] = 0.f;

    auto issue_stage = [&](int s, int k0) {
        uint32_t sb = smemB + (uint32_t)s * 20480u;
        #pragma unroll
        for (int i = 0; i < 2; i++) {
            int idx = tid + i * 256;
            int r = idx >> 2, ch = idx & 3;
            uint32_t doff = (uint32_t)(r * 80 + ch * 16);
            cp_async16(sb + doff, Ab + (size_t)r * lda + k0 + ch * 8);
            cp_async16(sb + 10240u + doff, Bp + (size_t)r * ldb + k0 + ch * 8);
        }
        CP_COMMIT();
    };

    const int nk = K >> 5;
    issue_stage(0, 0);
    issue_stage(1, 32);

    for (int k = 0; k < nk; k++) {
        CP_WAIT1();
        __syncthreads();
        if (k + 2 < nk) issue_stage((k + 2) % 3, (k + 2) * 32);
        else CP_COMMIT();

        const uint32_t sA = smemB + (uint32_t)((k % 3) * 20480);
        const uint32_t sB = sA + 10240u;
        #pragma unroll
        for (int s = 0; s < 2; s++) {
            uint32_t af[4][4], bf[4][2];
            #pragma unroll
            for (int m = 0; m < 4; m++)
                ldsm_x4(af[m], sA + aOff + (uint32_t)(m * 16 * 80 + s * 32));
            #pragma unroll
            for (int p = 0; p < 2; p++) {
                uint32_t rbv[4];
                ldsm_x4(rbv, sB + bOff + (uint32_t)(p * 16 * 80 + s * 32));
                bf[2 * p + 0][0] = rbv[0];
                bf[2 * p + 0][1] = rbv[1];
                bf[2 * p + 1][0] = rbv[2];
                bf[2 * p + 1][1] = rbv[3];
            }
            #pragma unroll
            for (int m = 0; m < 4; m++)
                #pragma unroll
                for (int n = 0; n < 4; n++)
                    mma_bf16(acc[m][n], af[m], bf[n]);
        }
        __syncthreads();
    }

    #pragma unroll
    for (int m = 0; m < 4; m++) {
        int r0 = rowBase + wm * 64 + m * 16 + g;
        #pragma unroll
        for (int n = 0; n < 4; n++) {
            int col = colBase + wn * 32 + n * 8 + 2 * t4;
            #pragma unroll
            for (int h = 0; h < 2; h++) {
                int r = r0 + h * 8;
                float e0 = acc[m][n][2 * h + 0];
                float e1 = acc[m][n][2 * h + 1];
                if (EPI == 2) {
                    float2 gp = *(const float2*)(g_mod + (r >> 11) * 3 * DM + 2 * DM + col);
                    float2 rp = *(const float2*)(res + (size_t)r * ldc + col);
                    e0 = rp.x + gp.x * e0;
                    e1 = rp.y + gp.y * e1;
                }
                if (EPI == 3) {
                    __nv_bfloat162 pk = __floats2bfloat162_rn(e0, e1);
                    *(__nv_bfloat162*)((__nv_bfloat16*)Cv + (size_t)r * ldc + col) = pk;
                } else {
                    float2 v2;
                    v2.x = e0;
                    v2.y = e1;
                    *(float2*)((float*)Cv + (size_t)r * ldc + col) = v2;
                }
            }
        }
    }
}

// ---------------- tf32 mma.sync GEMM (fp32 in) for delta GEMM ----------------
// EPI 1: softplus(acc + bias[n])  (branchless cheap softplus)
template <int EPI>
__global__ __launch_bounds__(256, 2)
void gemm_mma(int K, int lda, int ldb, int ldc,
              const float* __restrict__ A, const float* __restrict__ Bt,
              float* __restrict__ C,
              const float* __restrict__ bias) {
    extern __shared__ float smem[];
    const int tid = threadIdx.x;
    const int wid = tid >> 5, lane = tid & 31;
    const int g = lane >> 2, t4 = lane & 3;
    const int wm = wid & 1, wn = wid >> 1;
    const int rowBase = blockIdx.y * 128, colBase = blockIdx.x * 128;
    const float* Ab = A  + (size_t)rowBase * lda;
    const float* Bp = Bt + (size_t)colBase * ldb;
    const uint32_t smemB = smem_u32(smem);

    float acc[4][4][4];
    #pragma unroll
    for (int m = 0; m < 4; m++)
        #pragma unroll
        for (int n = 0; n < 4; n++)
            #pragma unroll
            for (int e = 0; e < 4; e++) acc[m][n][e] = 0.f;

    auto issue_stage = [&](int s, int k0) {
        uint32_t sb = smemB + (uint32_t)s * 8192u * 4u;
        #pragma unroll
        for (int i = 0; i < 4; i++) {
            int idx = tid + i * 256;
            int r = idx >> 3, cch = idx & 7;
            uint32_t doff = ((uint32_t)(r * 32 + ((cch ^ (r & 7)) << 2))) * 4u;
            cp_async16(sb + doff, Ab + (size_t)r * lda + k0 + cch * 4);
            cp_async16(sb + 16384u + doff, Bp + (size_t)r * ldb + k0 + cch * 4);
        }
        CP_COMMIT();
    };

    const int nk = K >> 5;
    issue_stage(0, 0);
    issue_stage(1, 32);

    for (int k = 0; k < nk; k++) {
        CP_WAIT1();
        __syncthreads();
        if (k + 2 < nk) issue_stage((k + 2) % 3, (k + 2) * 32);
        else CP_COMMIT();

        const float* sA = smem + (k % 3) * 8192;
        const float* sB = sA + 4096;
        const int aR = wm * 64 + g;
        const int bR = wn * 32 + g;
        #pragma unroll
        for (int kk = 0; kk < 4; kk++) {
            const int c0 = (((kk * 2 + 0) ^ g) << 2) + t4;
            const int c1 = (((kk * 2 + 1) ^ g) << 2) + t4;
            uint32_t af[4][4], bf[4][2];
            #pragma unroll
            for (int m = 0; m < 4; m++) {
                const float* p = sA + (aR + m * 16) * 32;
                af[m][0] = __float_as_uint(p[c0]);
                af[m][1] = __float_as_uint(p[8 * 32 + c0]);
                af[m][2] = __float_as_uint(p[c1]);
                af[m][3] = __float_as_uint(p[8 * 32 + c1]);
            }
            #pragma unroll
            for (int n = 0; n < 4; n++) {
                const float* p = sB + (bR + n * 8) * 32;
                bf[n][0] = __float_as_uint(p[c0]);
                bf[n][1] = __float_as_uint(p[c1]);
            }
            #pragma unroll
            for (int m = 0; m < 4; m++)
                #pragma unroll
                for (int n = 0; n < 4; n++)
                    mma_tf32(acc[m][n], af[m], bf[n]);
        }
        __syncthreads();
    }

    #pragma unroll
    for (int m = 0; m < 4; m++) {
        int r0 = rowBase + wm * 64 + m * 16 + g;
        #pragma unroll
        for (int n = 0; n < 4; n++) {
            int col = colBase + wn * 32 + n * 8 + 2 * t4;
            #pragma unroll
            for (int h = 0; h < 2; h++) {
                int r = r0 + h * 8;
                float e0 = acc[m][n][2 * h + 0];
                float e1 = acc[m][n][2 * h + 1];
                if (EPI == 1) {
                    float2 bb = *(const float2*)(bias + col);
                    e0 += bb.x;
                    e1 += bb.y;
                    e0 = fmaxf(e0, 0.f) + __logf(1.f + __expf(-fabsf(e0)));
                    e1 = fmaxf(e1, 0.f) + __logf(1.f + __expf(-fabsf(e1)));
                }
                float2 v2;
                v2.x = e0;
                v2.y = e1;
                *(float2*)(C + (size_t)r * ldc + col) = v2;
            }
        }
    }
}

// ---------------- launch ----------------
extern "C" void kernel_launch(void* const* d_in, const int* in_sizes, int n_in,
                              void* d_out, int out_size) {
    const float* x      = (const float*)d_in[0];
    const float* c      = (const float*)d_in[1];
    const float* W_in   = (const float*)d_in[2];
    const float* conv_w = (const float*)d_in[3];
    const float* conv_b = (const float*)d_in[4];
    const float* W_xp   = (const float*)d_in[5];
    const float* W_dt   = (const float*)d_in[6];
    const float* b_dt   = (const float*)d_in[7];
    const float* A_log  = (const float*)d_in[8];
    const float* D_skip = (const float*)d_in[9];
    const float* W_out  = (const float*)d_in[10];
    const float* W_ada  = (const float*)d_in[11];
    const float* b_ada  = (const float*)d_in[12];
    float* out = (float*)d_out;

    float *p_dbc, *p_delta, *p_WdtT;
    __nv_bfloat16 *p_hh, *p_xzh, *p_xch, *p_ymulh, *p_WinTh, *p_WxpTh, *p_WoutTh;
    cudaGetSymbolAddress((void**)&p_hh,     g_hh);
    cudaGetSymbolAddress((void**)&p_xzh,    g_xzh);
    cudaGetSymbolAddress((void**)&p_xch,    g_xch);
    cudaGetSymbolAddress((void**)&p_dbc,    g_dbc);
    cudaGetSymbolAddress((void**)&p_delta,  g_delta);
    cudaGetSymbolAddress((void**)&p_ymulh,  g_ymulh);
    cudaGetSymbolAddress((void**)&p_WinTh,  g_WinTh);
    cudaGetSymbolAddress((void**)&p_WxpTh,  g_WxpTh);
    cudaGetSymbolAddress((void**)&p_WdtT,   g_WdtT);
    cudaGetSymbolAddress((void**)&p_WoutTh, g_WoutTh);

    constexpr int SMEM_TF32 = 3 * 8192 * sizeof(float);   // 96 KB
    constexpr int SMEM_BF16 = 3 * 20480;                  // 60 KB
    cudaFuncSetAttribute(gemm_bf16<0>, cudaFuncAttributeMaxDynamicSharedMemorySize, SMEM_BF16);
    cudaFuncSetAttribute(gemm_bf16<2>, cudaFuncAttributeMaxDynamicSharedMemorySize, SMEM_BF16);
    cudaFuncSetAttribute(gemm_bf16<3>, cudaFuncAttributeMaxDynamicSharedMemorySize, SMEM_BF16);
    cudaFuncSetAttribute(gemm_mma<1>,  cudaFuncAttributeMaxDynamicSharedMemorySize, SMEM_TF32);

    // 0) fused ada + all weight transposes
    k_pre<<<6576, dim3(32, 8)>>>(c, W_ada, b_ada, W_in, W_xp, W_dt, W_out);
    // 1) LayerNorm + scale/shift -> bf16
    k_ln<<<ROWS, 256>>>(x);
    // 2) GEMM1 (bf16): h @ W_in -> xz (bf16)   [8192 x 4096, K=1024]
    gemm_bf16<3><<<dim3(2 * DI / 128, ROWS / 128), 256, SMEM_BF16>>>(
        DM, DM, DM, 2 * DI, p_hh, p_WinTh, p_xzh, nullptr);
    // 3) conv + silu (bf16 -> bf16)
    k_conv<<<(ROWS * DI / 2) / 256, 256>>>(conv_w, conv_b);
    // 4) GEMM2 (bf16): xc @ W_xproj(pad 128) -> dbc fp32 [8192 x 128, K=2048]
    gemm_bf16<0><<<dim3(1, ROWS / 128), 256, SMEM_BF16>>>(
        DI, DI, DI, DBCP, p_xch, p_WxpTh, p_dbc, nullptr);
    // 5) delta GEMM (tf32): dbc[:, :64] @ W_dt + b_dt, softplus -> delta fp32
    gemm_mma<1><<<dim3(DI / 128, ROWS / 128), 256, SMEM_TF32>>>(
        DTR, DBCP, DTR, DI, p_dbc, p_WdtT, p_delta, b_dt);
    // 6) scan pass 1: per-segment recurrence (segments 0..SEG-2)
    k_scan1<<<dim3(128, SEG - 1), 256>>>(A_log);
    // 7) combine: prefix over segments -> h_in per segment
    k_comb<<<(NCH * 4) / 256, 256>>>();
    // 8) scan pass 2: full scan per segment + skip + silu(z) gate -> ymul (bf16)
    k_scan2<<<dim3(128, SEG), 256>>>(A_log, D_skip, p_ymulh);
    // 9) GEMM3 (bf16): ymul @ W_out, fused residual + gate -> out
    gemm_bf16<2><<<dim3(DM / 128, ROWS / 128), 256, SMEM_BF16>>>(
        DI, DI, DI, DM, p_ymulh, p_WoutTh, out, x);
}